// round 1
// baseline (speedup 1.0000x reference)
#include <cuda_runtime.h>
#include <cuda_bf16.h>
#include <math.h>

#define B_ 4
#define S_ 2048
#define H_ 576
#define NH_ 9
#define NKV_ 3
#define HD_ 64
#define M_TOK (B_ * S_)   // 8192

// ---------------- scratch (device globals: no allocation allowed) ----------
__device__ float g_q[B_ * NH_ * S_ * HD_];   // [b][h][s][d] head-major
__device__ float g_k[B_ * NKV_ * S_ * HD_];
__device__ float g_v[B_ * NKV_ * S_ * HD_];
__device__ float g_o[B_ * S_ * NH_ * HD_];   // [b*S+s][h*64+d] token-major

// ---------------- SGEMM: C = A[M,K] * W[N,K]^T ------------------------------
// mode 0: scatter to head-major buffer [b][h][s][d]  (heads given, HD=64, S=2048)
// mode 1: plain row-major [M][N]
#define TBM 64
#define TBN 64
#define TBK 32
#define SST 68   // smem stride (padded, 16B-aligned)

__global__ __launch_bounds__(256) void gemm_xwt(
    const float* __restrict__ A, const float* __restrict__ W,
    float* __restrict__ C, int M, int N, int K, int heads, int mode)
{
    __shared__ float As[TBK * SST];
    __shared__ float Ws[TBK * SST];

    const int tid = threadIdx.x;
    const int m0 = blockIdx.y * TBM;
    const int n0 = blockIdx.x * TBN;
    const int tx = tid & 15;
    const int ty = tid >> 4;

    const int lr = tid >> 3;          // 0..31
    const int lc = (tid & 7) << 2;    // 0,4,...,28

    float acc[4][4];
#pragma unroll
    for (int i = 0; i < 4; i++)
#pragma unroll
        for (int j = 0; j < 4; j++) acc[i][j] = 0.f;

    for (int k0 = 0; k0 < K; k0 += TBK) {
#pragma unroll
        for (int rr = 0; rr < 2; rr++) {
            int r = lr + rr * 32;
            float4 av = *(const float4*)&A[(size_t)(m0 + r) * K + k0 + lc];
            As[(lc + 0) * SST + r] = av.x;
            As[(lc + 1) * SST + r] = av.y;
            As[(lc + 2) * SST + r] = av.z;
            As[(lc + 3) * SST + r] = av.w;
            float4 wv = *(const float4*)&W[(size_t)(n0 + r) * K + k0 + lc];
            Ws[(lc + 0) * SST + r] = wv.x;
            Ws[(lc + 1) * SST + r] = wv.y;
            Ws[(lc + 2) * SST + r] = wv.z;
            Ws[(lc + 3) * SST + r] = wv.w;
        }
        __syncthreads();
#pragma unroll
        for (int kk = 0; kk < TBK; kk++) {
            float4 a = *(const float4*)&As[kk * SST + ty * 4];
            float4 b = *(const float4*)&Ws[kk * SST + tx * 4];
            acc[0][0] += a.x * b.x; acc[0][1] += a.x * b.y; acc[0][2] += a.x * b.z; acc[0][3] += a.x * b.w;
            acc[1][0] += a.y * b.x; acc[1][1] += a.y * b.y; acc[1][2] += a.y * b.z; acc[1][3] += a.y * b.w;
            acc[2][0] += a.z * b.x; acc[2][1] += a.z * b.y; acc[2][2] += a.z * b.z; acc[2][3] += a.z * b.w;
            acc[3][0] += a.w * b.x; acc[3][1] += a.w * b.y; acc[3][2] += a.w * b.z; acc[3][3] += a.w * b.w;
        }
        __syncthreads();
    }

#pragma unroll
    for (int i = 0; i < 4; i++) {
        int m = m0 + ty * 4 + i;
#pragma unroll
        for (int j = 0; j < 4; j++) {
            int n = n0 + tx * 4 + j;
            float v = acc[i][j];
            if (mode == 0) {
                int b = m / S_, s = m - b * S_;
                int h = n >> 6, d = n & 63;
                C[(((size_t)b * heads + h) * S_ + s) * HD_ + d] = v;
            } else {
                C[(size_t)m * N + n] = v;
            }
        }
    }
}

// ---------------- RoPE (in place, head-major rows of 64) --------------------
__global__ void rope_kernel(float* __restrict__ buf, int rows, float scale)
{
    int idx = blockIdx.x * blockDim.x + threadIdx.x;
    int j = idx & 31;
    int row = idx >> 5;
    if (row >= rows) return;
    int s = row & (S_ - 1);
    double invf = pow(100000.0, -(double)(2 * j) / 64.0);
    double ang = (double)s * invf;
    float c = (float)cos(ang);
    float sn = (float)sin(ang);
    float* p = buf + (size_t)row * HD_;
    float x0 = p[j], x1 = p[j + 32];
    p[j]      = (x0 * c - x1 * sn) * scale;
    p[j + 32] = (x1 * c + x0 * sn) * scale;
}

// ---------------- Flash attention (causal, GQA) ------------------------------
// grid: (S/64, B*NH), block 256 (8 warps x 8 rows). Q pre-scaled by 1/8.
#define AST 68
#define ATT_SMEM (4 * 64 * AST * 4)

__global__ __launch_bounds__(256) void attn_kernel(
    const float* __restrict__ Q, const float* __restrict__ K,
    const float* __restrict__ V, float* __restrict__ O)
{
    extern __shared__ float sm[];
    float* Qs = sm;                    // [64][AST]  row-major [r][d]
    float* Kt = sm + 64 * AST;         // [64][AST]  transposed [d][c]
    float* Vs = sm + 2 * 64 * AST;     // [64][AST]  [c][d]
    float* Ps = sm + 3 * 64 * AST;     // [64][AST]  [r][c]

    const int bh = blockIdx.y;
    const int b = bh / NH_;
    const int h = bh - b * NH_;
    const int kvh = h / (NH_ / NKV_);
    const int q0 = (gridDim.x - 1 - blockIdx.x) * 64;   // heavy tiles first

    const int tid = threadIdx.x;
    const int w = tid >> 5;
    const int lane = tid & 31;

    const float* Qbase = Q + (((size_t)b * NH_ + h) * S_ + q0) * HD_;
    const float* Kbase = K + (((size_t)b * NKV_ + kvh) * S_) * HD_;
    const float* Vbase = V + (((size_t)b * NKV_ + kvh) * S_) * HD_;

    // load Q tile
    for (int i = tid; i < 64 * 16; i += 256) {
        int r = i >> 4, d4 = (i & 15) << 2;
        float4 v = *(const float4*)&Qbase[r * HD_ + d4];
        *(float4*)&Qs[r * AST + d4] = v;
    }

    float m_i[8], l_i[8], accv[8][2];
#pragma unroll
    for (int r = 0; r < 8; r++) {
        m_i[r] = -1e30f; l_i[r] = 0.f; accv[r][0] = 0.f; accv[r][1] = 0.f;
    }

    const int row_g = q0 + w * 8;
    const int nkt = q0 / 64 + 1;

    for (int kt = 0; kt < nkt; kt++) {
        const int k0 = kt * 64;
        __syncthreads();
        // load K (transposed) and V
        for (int i = tid; i < 64 * 16; i += 256) {
            int c = i >> 4, d4 = (i & 15) << 2;
            float4 kv = *(const float4*)&Kbase[(size_t)(k0 + c) * HD_ + d4];
            Kt[(d4 + 0) * AST + c] = kv.x;
            Kt[(d4 + 1) * AST + c] = kv.y;
            Kt[(d4 + 2) * AST + c] = kv.z;
            Kt[(d4 + 3) * AST + c] = kv.w;
            float4 vv = *(const float4*)&Vbase[(size_t)(k0 + c) * HD_ + d4];
            *(float4*)&Vs[c * AST + d4] = vv;
        }
        __syncthreads();

        // ---- scores: sc[r][0] = q_r . k_lane ; sc[r][1] = q_r . k_{lane+32}
        float sc[8][2];
#pragma unroll
        for (int r = 0; r < 8; r++) { sc[r][0] = 0.f; sc[r][1] = 0.f; }

        for (int d4 = 0; d4 < 64; d4 += 4) {
            float4 qv[8];
#pragma unroll
            for (int r = 0; r < 8; r++)
                qv[r] = *(const float4*)&Qs[(w * 8 + r) * AST + d4];
#pragma unroll
            for (int dd = 0; dd < 4; dd++) {
                float kv0 = Kt[(d4 + dd) * AST + lane];
                float kv1 = Kt[(d4 + dd) * AST + lane + 32];
#pragma unroll
                for (int r = 0; r < 8; r++) {
                    float qq = (&qv[r].x)[dd];
                    sc[r][0] += qq * kv0;
                    sc[r][1] += qq * kv1;
                }
            }
        }

        // causal mask (diagonal tile only)
        if (kt == nkt - 1) {
#pragma unroll
            for (int r = 0; r < 8; r++) {
                int grow = row_g + r;
                if (k0 + lane > grow)      sc[r][0] = -1e30f;
                if (k0 + lane + 32 > grow) sc[r][1] = -1e30f;
            }
        }

        // ---- online softmax
#pragma unroll
        for (int r = 0; r < 8; r++) {
            float mt = fmaxf(sc[r][0], sc[r][1]);
#pragma unroll
            for (int off = 16; off > 0; off >>= 1)
                mt = fmaxf(mt, __shfl_xor_sync(0xffffffffu, mt, off));
            float mn = fmaxf(m_i[r], mt);
            float alpha = expf(m_i[r] - mn);
            float p0 = expf(sc[r][0] - mn);
            float p1 = expf(sc[r][1] - mn);
            float ps = p0 + p1;
#pragma unroll
            for (int off = 16; off > 0; off >>= 1)
                ps += __shfl_xor_sync(0xffffffffu, ps, off);
            l_i[r] = l_i[r] * alpha + ps;
            m_i[r] = mn;
            accv[r][0] *= alpha;
            accv[r][1] *= alpha;
            Ps[(w * 8 + r) * AST + lane] = p0;
            Ps[(w * 8 + r) * AST + lane + 32] = p1;
        }
        __syncwarp();

        // ---- AV: acc[r][dl] += sum_c P[r][c] * V[c][dl]
        for (int c4 = 0; c4 < 64; c4 += 4) {
            float4 pv[8];
#pragma unroll
            for (int r = 0; r < 8; r++)
                pv[r] = *(const float4*)&Ps[(w * 8 + r) * AST + c4];
#pragma unroll
            for (int cc = 0; cc < 4; cc++) {
                float v0 = Vs[(c4 + cc) * AST + lane];
                float v1 = Vs[(c4 + cc) * AST + lane + 32];
#pragma unroll
                for (int r = 0; r < 8; r++) {
                    float pp = (&pv[r].x)[cc];
                    accv[r][0] += pp * v0;
                    accv[r][1] += pp * v1;
                }
            }
        }
    }

    // ---- epilogue: normalize, write token-major [b*S+s][h*64+d]
#pragma unroll
    for (int r = 0; r < 8; r++) {
        float inv = 1.f / l_i[r];
        int s = row_g + r;
        size_t base = (((size_t)b * S_ + s) * NH_ + h) * HD_;
        O[base + lane]      = accv[r][0] * inv;
        O[base + lane + 32] = accv[r][1] * inv;
    }
}

// ---------------- launch -----------------------------------------------------
extern "C" void kernel_launch(void* const* d_in, const int* in_sizes, int n_in,
                              void* d_out, int out_size)
{
    const float* x  = (const float*)d_in[0];
    const float* Wq = (const float*)d_in[1];
    const float* Wk = (const float*)d_in[2];
    const float* Wv = (const float*)d_in[3];
    const float* Wo = (const float*)d_in[4];
    float* out = (float*)d_out;

    float *qp, *kp, *vp, *op;
    cudaGetSymbolAddress((void**)&qp, g_q);
    cudaGetSymbolAddress((void**)&kp, g_k);
    cudaGetSymbolAddress((void**)&vp, g_v);
    cudaGetSymbolAddress((void**)&op, g_o);

    // projections
    gemm_xwt<<<dim3(H_ / TBN, M_TOK / TBM), 256>>>(x, Wq, qp, M_TOK, NH_ * HD_, H_, NH_, 0);
    gemm_xwt<<<dim3((NKV_ * HD_) / TBN, M_TOK / TBM), 256>>>(x, Wk, kp, M_TOK, NKV_ * HD_, H_, NKV_, 0);
    gemm_xwt<<<dim3((NKV_ * HD_) / TBN, M_TOK / TBM), 256>>>(x, Wv, vp, M_TOK, NKV_ * HD_, H_, NKV_, 0);

    // RoPE (+1/sqrt(HD) folded into q)
    {
        int rows_q = B_ * NH_ * S_;
        int rows_k = B_ * NKV_ * S_;
        rope_kernel<<<(rows_q * 32 + 255) / 256, 256>>>(qp, rows_q, 0.125f);
        rope_kernel<<<(rows_k * 32 + 255) / 256, 256>>>(kp, rows_k, 1.0f);
    }

    // attention
    cudaFuncSetAttribute(attn_kernel, cudaFuncAttributeMaxDynamicSharedMemorySize, ATT_SMEM);
    attn_kernel<<<dim3(S_ / 64, B_ * NH_), 256, ATT_SMEM>>>(qp, kp, vp, op);

    // output projection
    gemm_xwt<<<dim3(H_ / TBN, M_TOK / TBM), 256>>>(op, Wo, out, M_TOK, H_, NH_ * HD_, 0, 1);
}

// round 2
// speedup vs baseline: 1.5228x; 1.5228x over previous
#include <cuda_runtime.h>
#include <cuda_bf16.h>
#include <math.h>

#define B_ 4
#define S_ 2048
#define H_ 576
#define NH_ 9
#define NKV_ 3
#define HD_ 64
#define M_TOK (B_ * S_)   // 8192

// ---------------- scratch (device globals: no allocation allowed) ----------
__device__ float g_q[B_ * NH_ * S_ * HD_];   // [b][h][s][d] head-major
__device__ float g_k[B_ * NKV_ * S_ * HD_];
__device__ float g_v[B_ * NKV_ * S_ * HD_];
__device__ float g_o[B_ * S_ * NH_ * HD_];   // [b*S+s][h*64+d] token-major
__device__ float g_cos[S_ * 32];
__device__ float g_sin[S_ * 32];

// ---------------- SGEMM: C = A[M,K] * W[N,K]^T ------------------------------
// mode 0: scatter to head-major buffer [b][h][s][d]  (heads given, HD=64, S=2048)
// mode 1: plain row-major [M][N]
#define TBM 64
#define TBN 64
#define TBK 32
#define SST 68   // smem stride (padded, 16B-aligned)

__global__ __launch_bounds__(256) void gemm_xwt(
    const float* __restrict__ A, const float* __restrict__ W,
    float* __restrict__ C, int M, int N, int K, int heads, int mode)
{
    __shared__ float As[TBK * SST];
    __shared__ float Ws[TBK * SST];

    const int tid = threadIdx.x;
    const int m0 = blockIdx.y * TBM;
    const int n0 = blockIdx.x * TBN;
    const int tx = tid & 15;
    const int ty = tid >> 4;

    const int lr = tid >> 3;          // 0..31
    const int lc = (tid & 7) << 2;    // 0,4,...,28

    float acc[4][4];
#pragma unroll
    for (int i = 0; i < 4; i++)
#pragma unroll
        for (int j = 0; j < 4; j++) acc[i][j] = 0.f;

    for (int k0 = 0; k0 < K; k0 += TBK) {
#pragma unroll
        for (int rr = 0; rr < 2; rr++) {
            int r = lr + rr * 32;
            float4 av = *(const float4*)&A[(size_t)(m0 + r) * K + k0 + lc];
            As[(lc + 0) * SST + r] = av.x;
            As[(lc + 1) * SST + r] = av.y;
            As[(lc + 2) * SST + r] = av.z;
            As[(lc + 3) * SST + r] = av.w;
            float4 wv = *(const float4*)&W[(size_t)(n0 + r) * K + k0 + lc];
            Ws[(lc + 0) * SST + r] = wv.x;
            Ws[(lc + 1) * SST + r] = wv.y;
            Ws[(lc + 2) * SST + r] = wv.z;
            Ws[(lc + 3) * SST + r] = wv.w;
        }
        __syncthreads();
#pragma unroll
        for (int kk = 0; kk < TBK; kk++) {
            float4 a = *(const float4*)&As[kk * SST + ty * 4];
            float4 b = *(const float4*)&Ws[kk * SST + tx * 4];
            acc[0][0] += a.x * b.x; acc[0][1] += a.x * b.y; acc[0][2] += a.x * b.z; acc[0][3] += a.x * b.w;
            acc[1][0] += a.y * b.x; acc[1][1] += a.y * b.y; acc[1][2] += a.y * b.z; acc[1][3] += a.y * b.w;
            acc[2][0] += a.z * b.x; acc[2][1] += a.z * b.y; acc[2][2] += a.z * b.z; acc[2][3] += a.z * b.w;
            acc[3][0] += a.w * b.x; acc[3][1] += a.w * b.y; acc[3][2] += a.w * b.z; acc[3][3] += a.w * b.w;
        }
        __syncthreads();
    }

#pragma unroll
    for (int i = 0; i < 4; i++) {
        int m = m0 + ty * 4 + i;
#pragma unroll
        for (int j = 0; j < 4; j++) {
            int n = n0 + tx * 4 + j;
            float v = acc[i][j];
            if (mode == 0) {
                int b = m / S_, s = m - b * S_;
                int h = n >> 6, d = n & 63;
                C[(((size_t)b * heads + h) * S_ + s) * HD_ + d] = v;
            } else {
                C[(size_t)m * N + n] = v;
            }
        }
    }
}

// ---------------- RoPE table build (64K distinct angles, fp64 once) ---------
__global__ void rope_table_kernel()
{
    int idx = blockIdx.x * blockDim.x + threadIdx.x;   // 0 .. S_*32-1
    if (idx >= S_ * 32) return;
    int j = idx & 31;
    int s = idx >> 5;
    double invf = pow(100000.0, -(double)(2 * j) / 64.0);
    double ang = (double)s * invf;
    g_cos[idx] = (float)cos(ang);
    g_sin[idx] = (float)sin(ang);
}

// ---------------- RoPE apply (in place, head-major rows of 64) --------------
__global__ void rope_apply_kernel(float* __restrict__ buf, int rows, float scale)
{
    int idx = blockIdx.x * blockDim.x + threadIdx.x;
    int j = idx & 31;
    int row = idx >> 5;
    if (row >= rows) return;
    int s = row & (S_ - 1);
    float c  = g_cos[s * 32 + j];
    float sn = g_sin[s * 32 + j];
    float* p = buf + (size_t)row * HD_;
    float x0 = p[j], x1 = p[j + 32];
    p[j]      = (x0 * c - x1 * sn) * scale;
    p[j + 32] = (x1 * c + x0 * sn) * scale;
}

// ---------------- Flash attention (causal, GQA) ------------------------------
// grid: (S/64, B*NH), block 256 (8 warps x 8 rows). Q pre-scaled by 1/8.
#define AST 68
#define ATT_SMEM (4 * 64 * AST * 4)

__global__ __launch_bounds__(256) void attn_kernel(
    const float* __restrict__ Q, const float* __restrict__ K,
    const float* __restrict__ V, float* __restrict__ O)
{
    extern __shared__ float sm[];
    float* Qs = sm;                    // [64][AST]  row-major [r][d]
    float* Kt = sm + 64 * AST;         // [64][AST]  transposed [d][c]
    float* Vs = sm + 2 * 64 * AST;     // [64][AST]  [c][d]
    float* Ps = sm + 3 * 64 * AST;     // [64][AST]  [r][c]

    const int bh = blockIdx.y;
    const int b = bh / NH_;
    const int h = bh - b * NH_;
    const int kvh = h / (NH_ / NKV_);
    const int q0 = (gridDim.x - 1 - blockIdx.x) * 64;   // heavy tiles first

    const int tid = threadIdx.x;
    const int w = tid >> 5;
    const int lane = tid & 31;

    const float* Qbase = Q + (((size_t)b * NH_ + h) * S_ + q0) * HD_;
    const float* Kbase = K + (((size_t)b * NKV_ + kvh) * S_) * HD_;
    const float* Vbase = V + (((size_t)b * NKV_ + kvh) * S_) * HD_;

    // load Q tile
    for (int i = tid; i < 64 * 16; i += 256) {
        int r = i >> 4, d4 = (i & 15) << 2;
        float4 v = *(const float4*)&Qbase[r * HD_ + d4];
        *(float4*)&Qs[r * AST + d4] = v;
    }

    float m_i[8], l_i[8], accv[8][2];
#pragma unroll
    for (int r = 0; r < 8; r++) {
        m_i[r] = -1e30f; l_i[r] = 0.f; accv[r][0] = 0.f; accv[r][1] = 0.f;
    }

    const int row_g = q0 + w * 8;
    const int nkt = q0 / 64 + 1;

    for (int kt = 0; kt < nkt; kt++) {
        const int k0 = kt * 64;
        __syncthreads();
        // load K (transposed) and V
        for (int i = tid; i < 64 * 16; i += 256) {
            int c = i >> 4, d4 = (i & 15) << 2;
            float4 kv = *(const float4*)&Kbase[(size_t)(k0 + c) * HD_ + d4];
            Kt[(d4 + 0) * AST + c] = kv.x;
            Kt[(d4 + 1) * AST + c] = kv.y;
            Kt[(d4 + 2) * AST + c] = kv.z;
            Kt[(d4 + 3) * AST + c] = kv.w;
            float4 vv = *(const float4*)&Vbase[(size_t)(k0 + c) * HD_ + d4];
            *(float4*)&Vs[c * AST + d4] = vv;
        }
        __syncthreads();

        // ---- scores: sc[r][0] = q_r . k_lane ; sc[r][1] = q_r . k_{lane+32}
        float sc[8][2];
#pragma unroll
        for (int r = 0; r < 8; r++) { sc[r][0] = 0.f; sc[r][1] = 0.f; }

        for (int d4 = 0; d4 < 64; d4 += 4) {
            float4 qv[8];
#pragma unroll
            for (int r = 0; r < 8; r++)
                qv[r] = *(const float4*)&Qs[(w * 8 + r) * AST + d4];
#pragma unroll
            for (int dd = 0; dd < 4; dd++) {
                float kv0 = Kt[(d4 + dd) * AST + lane];
                float kv1 = Kt[(d4 + dd) * AST + lane + 32];
#pragma unroll
                for (int r = 0; r < 8; r++) {
                    float qq = (&qv[r].x)[dd];
                    sc[r][0] += qq * kv0;
                    sc[r][1] += qq * kv1;
                }
            }
        }

        // causal mask (diagonal tile only)
        if (kt == nkt - 1) {
#pragma unroll
            for (int r = 0; r < 8; r++) {
                int grow = row_g + r;
                if (k0 + lane > grow)      sc[r][0] = -1e30f;
                if (k0 + lane + 32 > grow) sc[r][1] = -1e30f;
            }
        }

        // ---- online softmax
#pragma unroll
        for (int r = 0; r < 8; r++) {
            float mt = fmaxf(sc[r][0], sc[r][1]);
#pragma unroll
            for (int off = 16; off > 0; off >>= 1)
                mt = fmaxf(mt, __shfl_xor_sync(0xffffffffu, mt, off));
            float mn = fmaxf(m_i[r], mt);
            float alpha = expf(m_i[r] - mn);
            float p0 = expf(sc[r][0] - mn);
            float p1 = expf(sc[r][1] - mn);
            float ps = p0 + p1;
#pragma unroll
            for (int off = 16; off > 0; off >>= 1)
                ps += __shfl_xor_sync(0xffffffffu, ps, off);
            l_i[r] = l_i[r] * alpha + ps;
            m_i[r] = mn;
            accv[r][0] *= alpha;
            accv[r][1] *= alpha;
            Ps[(w * 8 + r) * AST + lane] = p0;
            Ps[(w * 8 + r) * AST + lane + 32] = p1;
        }
        __syncwarp();

        // ---- AV: acc[r][dl] += sum_c P[r][c] * V[c][dl]
        for (int c4 = 0; c4 < 64; c4 += 4) {
            float4 pv[8];
#pragma unroll
            for (int r = 0; r < 8; r++)
                pv[r] = *(const float4*)&Ps[(w * 8 + r) * AST + c4];
#pragma unroll
            for (int cc = 0; cc < 4; cc++) {
                float v0 = Vs[(c4 + cc) * AST + lane];
                float v1 = Vs[(c4 + cc) * AST + lane + 32];
#pragma unroll
                for (int r = 0; r < 8; r++) {
                    float pp = (&pv[r].x)[cc];
                    accv[r][0] += pp * v0;
                    accv[r][1] += pp * v1;
                }
            }
        }
    }

    // ---- epilogue: normalize, write token-major [b*S+s][h*64+d]
#pragma unroll
    for (int r = 0; r < 8; r++) {
        float inv = 1.f / l_i[r];
        int s = row_g + r;
        size_t base = (((size_t)b * S_ + s) * NH_ + h) * HD_;
        O[base + lane]      = accv[r][0] * inv;
        O[base + lane + 32] = accv[r][1] * inv;
    }
}

// ---------------- launch -----------------------------------------------------
extern "C" void kernel_launch(void* const* d_in, const int* in_sizes, int n_in,
                              void* d_out, int out_size)
{
    const float* x  = (const float*)d_in[0];
    const float* Wq = (const float*)d_in[1];
    const float* Wk = (const float*)d_in[2];
    const float* Wv = (const float*)d_in[3];
    const float* Wo = (const float*)d_in[4];
    float* out = (float*)d_out;

    float *qp, *kp, *vp, *op;
    cudaGetSymbolAddress((void**)&qp, g_q);
    cudaGetSymbolAddress((void**)&kp, g_k);
    cudaGetSymbolAddress((void**)&vp, g_v);
    cudaGetSymbolAddress((void**)&op, g_o);

    // RoPE table (cheap, runs concurrently-independent of projections)
    rope_table_kernel<<<(S_ * 32 + 255) / 256, 256>>>();

    // projections
    gemm_xwt<<<dim3(H_ / TBN, M_TOK / TBM), 256>>>(x, Wq, qp, M_TOK, NH_ * HD_, H_, NH_, 0);
    gemm_xwt<<<dim3((NKV_ * HD_) / TBN, M_TOK / TBM), 256>>>(x, Wk, kp, M_TOK, NKV_ * HD_, H_, NKV_, 0);
    gemm_xwt<<<dim3((NKV_ * HD_) / TBN, M_TOK / TBM), 256>>>(x, Wv, vp, M_TOK, NKV_ * HD_, H_, NKV_, 0);

    // RoPE apply (+1/sqrt(HD) folded into q)
    {
        int rows_q = B_ * NH_ * S_;
        int rows_k = B_ * NKV_ * S_;
        rope_apply_kernel<<<(rows_q * 32 + 255) / 256, 256>>>(qp, rows_q, 0.125f);
        rope_apply_kernel<<<(rows_k * 32 + 255) / 256, 256>>>(kp, rows_k, 1.0f);
    }

    // attention
    cudaFuncSetAttribute(attn_kernel, cudaFuncAttributeMaxDynamicSharedMemorySize, ATT_SMEM);
    attn_kernel<<<dim3(S_ / 64, B_ * NH_), 256, ATT_SMEM>>>(qp, kp, vp, op);

    // output projection
    gemm_xwt<<<dim3(H_ / TBN, M_TOK / TBM), 256>>>(op, Wo, out, M_TOK, H_, NH_ * HD_, 0, 1);
}

// round 3
// speedup vs baseline: 2.1022x; 1.3805x over previous
#include <cuda_runtime.h>
#include <cuda_bf16.h>
#include <math.h>

#define B_ 4
#define S_ 2048
#define H_ 576
#define NH_ 9
#define NKV_ 3
#define HD_ 64
#define M_TOK (B_ * S_)   // 8192

// ---------------- scratch ----------------------------------------------------
__device__ float g_q[B_ * NH_ * S_ * HD_];   // [b][h][s][d]
__device__ float g_k[B_ * NKV_ * S_ * HD_];
__device__ float g_v[B_ * NKV_ * S_ * HD_];
__device__ float g_o[B_ * S_ * NH_ * HD_];   // token-major
__device__ float g_cos[S_ * 32];
__device__ float g_sin[S_ * 32];

// ---------------- tf32 helpers ------------------------------------------------
__device__ __forceinline__ unsigned tf32_hi(float x) {
    unsigned r;
    asm("cvt.rna.tf32.f32 %0, %1;" : "=r"(r) : "f"(x));
    return r;
}
__device__ __forceinline__ void split2(float x, unsigned& hi, unsigned& lo) {
    hi = tf32_hi(x);
    lo = __float_as_uint(x - __uint_as_float(hi));
}
__device__ __forceinline__ void mma8(float* c,
    unsigned a0, unsigned a1, unsigned a2, unsigned a3,
    unsigned b0, unsigned b1)
{
    asm volatile(
        "mma.sync.aligned.m16n8k8.row.col.f32.tf32.tf32.f32 "
        "{%0,%1,%2,%3},{%4,%5,%6,%7},{%8,%9},{%0,%1,%2,%3};"
        : "+f"(c[0]), "+f"(c[1]), "+f"(c[2]), "+f"(c[3])
        : "r"(a0), "r"(a1), "r"(a2), "r"(a3), "r"(b0), "r"(b1));
}
// 3xTF32 split mma: d += a*b with ~fp32 precision
__device__ __forceinline__ void mma_split(float* c,
    const unsigned* ah, const unsigned* al,
    const unsigned* bh, const unsigned* bl)
{
    mma8(c, ah[0], ah[1], ah[2], ah[3], bh[0], bh[1]);
    mma8(c, ah[0], ah[1], ah[2], ah[3], bl[0], bl[1]);
    mma8(c, al[0], al[1], al[2], al[3], bh[0], bh[1]);
}

// ---------------- tensor-core GEMM: C = A[M,K] * W[N,K]^T ---------------------
// block 256 thr (8 warps), tile M=128 N=64 K=32. warp tile 32x32.
#define GST 36   // smem stride: bank = 4g+t conflict-free

__global__ __launch_bounds__(256) void gemm_tc(
    const float* __restrict__ A, const float* __restrict__ W,
    float* __restrict__ C, int M, int N, int K, int heads, int mode)
{
    __shared__ float As[128 * GST];
    __shared__ float Ws[64 * GST];

    const int tid = threadIdx.x;
    const int w = tid >> 5;
    const int lane = tid & 31;
    const int g = lane >> 2;
    const int t = lane & 3;
    const int wm = w >> 1;     // 0..3
    const int wn = w & 1;      // 0..1
    const int m0 = blockIdx.y * 128;
    const int n0 = blockIdx.x * 64;

    float acc[2][4][4];
#pragma unroll
    for (int mt = 0; mt < 2; mt++)
#pragma unroll
        for (int nt = 0; nt < 4; nt++)
#pragma unroll
            for (int r = 0; r < 4; r++) acc[mt][nt][r] = 0.f;

    for (int k0 = 0; k0 < K; k0 += 32) {
        // load A 128x32, W 64x32
#pragma unroll
        for (int i = tid; i < 128 * 8; i += 256) {
            int r = i >> 3, c4 = (i & 7) << 2;
            float4 v = *(const float4*)&A[(size_t)(m0 + r) * K + k0 + c4];
            *(float4*)&As[r * GST + c4] = v;
        }
#pragma unroll
        for (int i = tid; i < 64 * 8; i += 256) {
            int r = i >> 3, c4 = (i & 7) << 2;
            float4 v = *(const float4*)&W[(size_t)(n0 + r) * K + k0 + c4];
            *(float4*)&Ws[r * GST + c4] = v;
        }
        __syncthreads();

#pragma unroll
        for (int ks = 0; ks < 4; ks++) {
            const int k8 = ks * 8;
            unsigned ah[2][4], al[2][4], bh[4][2], bl[4][2];
#pragma unroll
            for (int mt = 0; mt < 2; mt++) {
                int R = wm * 32 + mt * 16;
                split2(As[(R + g) * GST + k8 + t],     ah[mt][0], al[mt][0]);
                split2(As[(R + g + 8) * GST + k8 + t], ah[mt][1], al[mt][1]);
                split2(As[(R + g) * GST + k8 + t + 4],     ah[mt][2], al[mt][2]);
                split2(As[(R + g + 8) * GST + k8 + t + 4], ah[mt][3], al[mt][3]);
            }
#pragma unroll
            for (int nt = 0; nt < 4; nt++) {
                int Cc = wn * 32 + nt * 8;
                split2(Ws[(Cc + g) * GST + k8 + t],     bh[nt][0], bl[nt][0]);
                split2(Ws[(Cc + g) * GST + k8 + t + 4], bh[nt][1], bl[nt][1]);
            }
#pragma unroll
            for (int mt = 0; mt < 2; mt++)
#pragma unroll
                for (int nt = 0; nt < 4; nt++)
                    mma_split(acc[mt][nt], ah[mt], al[mt], bh[nt], bl[nt]);
        }
        __syncthreads();
    }

    // epilogue
#pragma unroll
    for (int mt = 0; mt < 2; mt++)
#pragma unroll
        for (int nt = 0; nt < 4; nt++)
#pragma unroll
            for (int r = 0; r < 4; r++) {
                int row = m0 + wm * 32 + mt * 16 + g + ((r >> 1) << 3);
                int col = n0 + wn * 32 + nt * 8 + t * 2 + (r & 1);
                float v = acc[mt][nt][r];
                if (mode == 0) {
                    int b = row / S_, s = row - b * S_;
                    int h = col >> 6, d = col & 63;
                    C[(((size_t)b * heads + h) * S_ + s) * HD_ + d] = v;
                } else {
                    C[(size_t)row * N + col] = v;
                }
            }
}

// ---------------- RoPE --------------------------------------------------------
__global__ void rope_table_kernel()
{
    int idx = blockIdx.x * blockDim.x + threadIdx.x;
    if (idx >= S_ * 32) return;
    int j = idx & 31;
    int s = idx >> 5;
    double invf = pow(100000.0, -(double)(2 * j) / 64.0);
    double ang = (double)s * invf;
    g_cos[idx] = (float)cos(ang);
    g_sin[idx] = (float)sin(ang);
}

__global__ void rope_apply_kernel(float* __restrict__ buf, int rows, float scale)
{
    int idx = blockIdx.x * blockDim.x + threadIdx.x;
    int j = idx & 31;
    int row = idx >> 5;
    if (row >= rows) return;
    int s = row & (S_ - 1);
    float c  = g_cos[s * 32 + j];
    float sn = g_sin[s * 32 + j];
    float* p = buf + (size_t)row * HD_;
    float x0 = p[j], x1 = p[j + 32];
    p[j]      = (x0 * c - x1 * sn) * scale;
    p[j + 32] = (x1 * c + x0 * sn) * scale;
}

// ---------------- Flash attention (tensor cores, causal, GQA) -----------------
// block 256 thr (8 warps). Q tile 64, K tile 64.
// mma warp grid: 2 (m) x 4 (n). warp tile 32x16.
#define AST 68   // stride: 4g+t conflict-free fragment reads
#define ATT_SMEM ((4 * 64 * AST + 128) * 4)

__global__ __launch_bounds__(256) void attn_tc_kernel(
    const float* __restrict__ Q, const float* __restrict__ K,
    const float* __restrict__ V, float* __restrict__ O)
{
    extern __shared__ float sm[];
    float* Qs = sm;                        // [64 rows][AST] (dims)
    float* Ks = sm + 64 * AST;             // [64 kv-rows][AST] (dims)
    float* Vt = sm + 2 * 64 * AST;         // [64 dims][AST] (kv pos)
    float* Ss = sm + 3 * 64 * AST;         // scores / probs [64][AST]
    float* salpha = sm + 4 * 64 * AST;     // [64]
    float* slinv  = salpha + 64;           // [64]

    const int bh = blockIdx.y;
    const int b = bh / NH_;
    const int h = bh - b * NH_;
    const int kvh = h / (NH_ / NKV_);
    const int q0 = (gridDim.x - 1 - blockIdx.x) * 64;

    const int tid = threadIdx.x;
    const int w = tid >> 5;
    const int lane = tid & 31;
    const int g = lane >> 2;
    const int t = lane & 3;
    const int wm = w >> 2;     // 0..1
    const int wn = w & 3;      // 0..3

    const float* Qbase = Q + (((size_t)b * NH_ + h) * S_ + q0) * HD_;
    const float* Kbase = K + (((size_t)b * NKV_ + kvh) * S_) * HD_;
    const float* Vbase = V + (((size_t)b * NKV_ + kvh) * S_) * HD_;

    // load Q tile
    for (int i = tid; i < 64 * 16; i += 256) {
        int r = i >> 4, d4 = (i & 15) << 2;
        float4 v = *(const float4*)&Qbase[r * HD_ + d4];
        *(float4*)&Qs[r * AST + d4] = v;
    }

    // O accumulators (mma fragment layout), softmax state
    float acc[2][2][4];
#pragma unroll
    for (int mt = 0; mt < 2; mt++)
#pragma unroll
        for (int nt = 0; nt < 2; nt++)
#pragma unroll
            for (int r = 0; r < 4; r++) acc[mt][nt][r] = 0.f;

    float m_i[8], l_i[8];
#pragma unroll
    for (int r = 0; r < 8; r++) { m_i[r] = -1e30f; l_i[r] = 0.f; }

    const int nkt = q0 / 64 + 1;

    for (int kt = 0; kt < nkt; kt++) {
        const int k0 = kt * 64;
        __syncthreads();   // prev AV done (Ks/Vt/Ss reuse safe)

        // load K tile [c][d]; V transposed [d][c]
        for (int i = tid; i < 64 * 16; i += 256) {
            int c = i >> 4, d4 = (i & 15) << 2;
            float4 kv = *(const float4*)&Kbase[(size_t)(k0 + c) * HD_ + d4];
            *(float4*)&Ks[c * AST + d4] = kv;
            float4 vv = *(const float4*)&Vbase[(size_t)(k0 + c) * HD_ + d4];
            Vt[(d4 + 0) * AST + c] = vv.x;
            Vt[(d4 + 1) * AST + c] = vv.y;
            Vt[(d4 + 2) * AST + c] = vv.z;
            Vt[(d4 + 3) * AST + c] = vv.w;
        }
        __syncthreads();

        // ---- scores: warp tile 32x16 at (wm*32, wn*16)
        float sacc[2][2][4];
#pragma unroll
        for (int mt = 0; mt < 2; mt++)
#pragma unroll
            for (int nt = 0; nt < 2; nt++)
#pragma unroll
                for (int r = 0; r < 4; r++) sacc[mt][nt][r] = 0.f;

#pragma unroll
        for (int ks = 0; ks < 8; ks++) {
            const int k8 = ks * 8;
            unsigned ah[2][4], al[2][4], bh[2][2], bl[2][2];
#pragma unroll
            for (int mt = 0; mt < 2; mt++) {
                int R = wm * 32 + mt * 16;
                split2(Qs[(R + g) * AST + k8 + t],         ah[mt][0], al[mt][0]);
                split2(Qs[(R + g + 8) * AST + k8 + t],     ah[mt][1], al[mt][1]);
                split2(Qs[(R + g) * AST + k8 + t + 4],     ah[mt][2], al[mt][2]);
                split2(Qs[(R + g + 8) * AST + k8 + t + 4], ah[mt][3], al[mt][3]);
            }
#pragma unroll
            for (int nt = 0; nt < 2; nt++) {
                int Cc = wn * 16 + nt * 8;
                split2(Ks[(Cc + g) * AST + k8 + t],     bh[nt][0], bl[nt][0]);
                split2(Ks[(Cc + g) * AST + k8 + t + 4], bh[nt][1], bl[nt][1]);
            }
#pragma unroll
            for (int mt = 0; mt < 2; mt++)
#pragma unroll
                for (int nt = 0; nt < 2; nt++)
                    mma_split(sacc[mt][nt], ah[mt], al[mt], bh[nt], bl[nt]);
        }

        // write scores (+ causal mask on diagonal tile)
        const bool diag = (kt == nkt - 1);
#pragma unroll
        for (int mt = 0; mt < 2; mt++)
#pragma unroll
            for (int nt = 0; nt < 2; nt++)
#pragma unroll
                for (int r = 0; r < 4; r++) {
                    int row = wm * 32 + mt * 16 + g + ((r >> 1) << 3);
                    int col = wn * 16 + nt * 8 + t * 2 + (r & 1);
                    float v = sacc[mt][nt][r];
                    if (diag && (k0 + col > q0 + row)) v = -1e30f;
                    Ss[row * AST + col] = v;
                }
        __syncthreads();

        // ---- online softmax: warp w handles rows w*8 .. w*8+7
#pragma unroll
        for (int r = 0; r < 8; r++) {
            int row = w * 8 + r;
            float s0 = Ss[row * AST + lane];
            float s1 = Ss[row * AST + lane + 32];
            float mt2 = fmaxf(s0, s1);
#pragma unroll
            for (int off = 16; off > 0; off >>= 1)
                mt2 = fmaxf(mt2, __shfl_xor_sync(0xffffffffu, mt2, off));
            float mn = fmaxf(m_i[r], mt2);
            float alpha = __expf(m_i[r] - mn);
            float p0 = __expf(s0 - mn);
            float p1 = __expf(s1 - mn);
            float ps = p0 + p1;
#pragma unroll
            for (int off = 16; off > 0; off >>= 1)
                ps += __shfl_xor_sync(0xffffffffu, ps, off);
            l_i[r] = l_i[r] * alpha + ps;
            m_i[r] = mn;
            Ss[row * AST + lane] = p0;
            Ss[row * AST + lane + 32] = p1;
            if (lane == 0) salpha[row] = alpha;
        }
        __syncthreads();

        // ---- AV: rescale acc, then O += P x V. warp tile 32x16 (n = dims 16)
        {
            float a0 = salpha[wm * 32 + g];
            float a1 = salpha[wm * 32 + g + 8];
            float a2 = salpha[wm * 32 + 16 + g];
            float a3 = salpha[wm * 32 + 16 + g + 8];
#pragma unroll
            for (int nt = 0; nt < 2; nt++) {
                acc[0][nt][0] *= a0; acc[0][nt][1] *= a0;
                acc[0][nt][2] *= a1; acc[0][nt][3] *= a1;
                acc[1][nt][0] *= a2; acc[1][nt][1] *= a2;
                acc[1][nt][2] *= a3; acc[1][nt][3] *= a3;
            }
        }

#pragma unroll
        for (int ks = 0; ks < 8; ks++) {
            const int k8 = ks * 8;
            unsigned ah[2][4], al[2][4], bh[2][2], bl[2][2];
#pragma unroll
            for (int mt = 0; mt < 2; mt++) {
                int R = wm * 32 + mt * 16;
                split2(Ss[(R + g) * AST + k8 + t],         ah[mt][0], al[mt][0]);
                split2(Ss[(R + g + 8) * AST + k8 + t],     ah[mt][1], al[mt][1]);
                split2(Ss[(R + g) * AST + k8 + t + 4],     ah[mt][2], al[mt][2]);
                split2(Ss[(R + g + 8) * AST + k8 + t + 4], ah[mt][3], al[mt][3]);
            }
#pragma unroll
            for (int nt = 0; nt < 2; nt++) {
                int Cc = wn * 16 + nt * 8;
                split2(Vt[(Cc + g) * AST + k8 + t],     bh[nt][0], bl[nt][0]);
                split2(Vt[(Cc + g) * AST + k8 + t + 4], bh[nt][1], bl[nt][1]);
            }
#pragma unroll
            for (int mt = 0; mt < 2; mt++)
#pragma unroll
                for (int nt = 0; nt < 2; nt++)
                    mma_split(acc[mt][nt], ah[mt], al[mt], bh[nt], bl[nt]);
        }
    }

    // ---- epilogue
#pragma unroll
    for (int r = 0; r < 8; r++)
        if (lane == 0) slinv[w * 8 + r] = 1.f / l_i[r];
    __syncthreads();

#pragma unroll
    for (int mt = 0; mt < 2; mt++) {
        int R = wm * 32 + mt * 16;
        float i0 = slinv[R + g];
        float i1 = slinv[R + g + 8];
#pragma unroll
        for (int nt = 0; nt < 2; nt++)
#pragma unroll
            for (int r = 0; r < 4; r++) {
                int row = R + g + ((r >> 1) << 3);
                int col = wn * 16 + nt * 8 + t * 2 + (r & 1);
                float v = acc[mt][nt][r] * ((r >> 1) ? i1 : i0);
                int s = q0 + row;
                O[(((size_t)b * S_ + s) * NH_ + h) * HD_ + col] = v;
            }
    }
}

// ---------------- launch -------------------------------------------------------
extern "C" void kernel_launch(void* const* d_in, const int* in_sizes, int n_in,
                              void* d_out, int out_size)
{
    const float* x  = (const float*)d_in[0];
    const float* Wq = (const float*)d_in[1];
    const float* Wk = (const float*)d_in[2];
    const float* Wv = (const float*)d_in[3];
    const float* Wo = (const float*)d_in[4];
    float* out = (float*)d_out;

    float *qp, *kp, *vp, *op;
    cudaGetSymbolAddress((void**)&qp, g_q);
    cudaGetSymbolAddress((void**)&kp, g_k);
    cudaGetSymbolAddress((void**)&vp, g_v);
    cudaGetSymbolAddress((void**)&op, g_o);

    rope_table_kernel<<<(S_ * 32 + 255) / 256, 256>>>();

    gemm_tc<<<dim3(9, 64), 256>>>(x, Wq, qp, M_TOK, NH_ * HD_, H_, NH_, 0);
    gemm_tc<<<dim3(3, 64), 256>>>(x, Wk, kp, M_TOK, NKV_ * HD_, H_, NKV_, 0);
    gemm_tc<<<dim3(3, 64), 256>>>(x, Wv, vp, M_TOK, NKV_ * HD_, H_, NKV_, 0);

    {
        int rows_q = B_ * NH_ * S_;
        int rows_k = B_ * NKV_ * S_;
        rope_apply_kernel<<<(rows_q * 32 + 255) / 256, 256>>>(qp, rows_q, 0.125f);
        rope_apply_kernel<<<(rows_k * 32 + 255) / 256, 256>>>(kp, rows_k, 1.0f);
    }

    cudaFuncSetAttribute(attn_tc_kernel, cudaFuncAttributeMaxDynamicSharedMemorySize, ATT_SMEM);
    attn_tc_kernel<<<dim3(S_ / 64, B_ * NH_), 256, ATT_SMEM>>>(qp, kp, vp, op);

    gemm_tc<<<dim3(9, 64), 256>>>(op, Wo, out, M_TOK, H_, NH_ * HD_, 0, 1);
}

// round 5
// speedup vs baseline: 3.2800x; 1.5603x over previous
#include <cuda_runtime.h>
#include <cuda_bf16.h>
#include <math.h>

#define B_ 4
#define S_ 2048
#define H_ 576
#define NH_ 9
#define NKV_ 3
#define HD_ 64
#define M_TOK (B_ * S_)   // 8192
#define K2_ (H_ / 2)      // 288 packed u32 per token row

// ---------------- scratch -----------------------------------------------------
__device__ float g_q[B_ * NH_ * S_ * HD_];
__device__ float g_k[B_ * NKV_ * S_ * HD_];
__device__ float g_v[B_ * NKV_ * S_ * HD_];
__device__ float g_cos[S_ * 32];
__device__ float g_sin[S_ * 32];

// packed bf16x2 hi/lo planes
__device__ unsigned g_xh[M_TOK * K2_],  g_xl[M_TOK * K2_];
__device__ unsigned g_wqh[H_ * K2_],    g_wql[H_ * K2_];
__device__ unsigned g_wkh[NKV_ * HD_ * K2_], g_wkl[NKV_ * HD_ * K2_];
__device__ unsigned g_wvh[NKV_ * HD_ * K2_], g_wvl[NKV_ * HD_ * K2_];
__device__ unsigned g_woh[H_ * K2_],    g_wol[H_ * K2_];
__device__ unsigned g_qh[B_ * NH_ * S_ * 32],  g_ql[B_ * NH_ * S_ * 32];
__device__ unsigned g_kh[B_ * NKV_ * S_ * 32], g_kl[B_ * NKV_ * S_ * 32];
__device__ unsigned g_vth[B_ * NKV_ * HD_ * (S_ / 2)], g_vtl[B_ * NKV_ * HD_ * (S_ / 2)];
__device__ unsigned g_oh[M_TOK * K2_],  g_ol[M_TOK * K2_];

// ---------------- helpers ------------------------------------------------------
__device__ __forceinline__ void split_pack(float x0, float x1, unsigned& hi, unsigned& lo)
{
    __nv_bfloat162 h = __float22bfloat162_rn(make_float2(x0, x1));
    float2 hf = __bfloat1622float2(h);
    __nv_bfloat162 l = __float22bfloat162_rn(make_float2(x0 - hf.x, x1 - hf.y));
    hi = *reinterpret_cast<unsigned*>(&h);
    lo = *reinterpret_cast<unsigned*>(&l);
}

__device__ __forceinline__ void mma16(float* c,
    unsigned a0, unsigned a1, unsigned a2, unsigned a3,
    unsigned b0, unsigned b1)
{
    asm volatile(
        "mma.sync.aligned.m16n8k16.row.col.f32.bf16.bf16.f32 "
        "{%0,%1,%2,%3},{%4,%5,%6,%7},{%8,%9},{%0,%1,%2,%3};"
        : "+f"(c[0]), "+f"(c[1]), "+f"(c[2]), "+f"(c[3])
        : "r"(a0), "r"(a1), "r"(a2), "r"(a3), "r"(b0), "r"(b1));
}
__device__ __forceinline__ void mma_split(float* c,
    const unsigned* ah, const unsigned* al,
    const unsigned* bh, const unsigned* bl)
{
    mma16(c, ah[0], ah[1], ah[2], ah[3], bh[0], bh[1]);
    mma16(c, ah[0], ah[1], ah[2], ah[3], bl[0], bl[1]);
    mma16(c, al[0], al[1], al[2], al[3], bh[0], bh[1]);
}

// ---------------- prepass: split float matrix to packed planes ------------------
__global__ void split_pack_kernel(const float* __restrict__ src,
                                  unsigned* __restrict__ hi, unsigned* __restrict__ lo, int n2)
{
    int i = blockIdx.x * blockDim.x + threadIdx.x;
    if (i >= n2) return;
    float2 v = ((const float2*)src)[i];
    split_pack(v.x, v.y, hi[i], lo[i]);
}

// ---------------- tensor-core GEMM on packed planes -----------------------------
// C = A[M,K] * W[N,K]^T, tile 128x64, K-step 64 (32 u32). 8 warps, warp tile 32x32.
#define GST 36
#define GEMM_SMEM ((128 * GST * 2 + 64 * GST * 2) * 4)

__global__ __launch_bounds__(256) void gemm_tc(
    const unsigned* __restrict__ Ahg, const unsigned* __restrict__ Alg,
    const unsigned* __restrict__ Whg, const unsigned* __restrict__ Wlg,
    float* __restrict__ C, int N, int K2, int heads, int mode)
{
    extern __shared__ unsigned smu[];
    unsigned* Ah = smu;
    unsigned* Al = smu + 128 * GST;
    unsigned* Wh = smu + 2 * 128 * GST;
    unsigned* Wl = Wh + 64 * GST;

    const int tid = threadIdx.x;
    const int w = tid >> 5;
    const int lane = tid & 31;
    const int g = lane >> 2;
    const int t = lane & 3;
    const int wm = w >> 1;
    const int wn = w & 1;
    const int m0 = blockIdx.y * 128;
    const int n0 = blockIdx.x * 64;

    float acc[2][4][4];
#pragma unroll
    for (int mt = 0; mt < 2; mt++)
#pragma unroll
        for (int nt = 0; nt < 4; nt++)
#pragma unroll
            for (int r = 0; r < 4; r++) acc[mt][nt][r] = 0.f;

    for (int k2 = 0; k2 < K2; k2 += 32) {
#pragma unroll
        for (int i = tid; i < 128 * 8; i += 256) {
            int r = i >> 3, c4 = (i & 7) << 2;
            *(uint4*)&Ah[r * GST + c4] = *(const uint4*)&Ahg[(size_t)(m0 + r) * K2 + k2 + c4];
            *(uint4*)&Al[r * GST + c4] = *(const uint4*)&Alg[(size_t)(m0 + r) * K2 + k2 + c4];
        }
#pragma unroll
        for (int i = tid; i < 64 * 8; i += 256) {
            int r = i >> 3, c4 = (i & 7) << 2;
            *(uint4*)&Wh[r * GST + c4] = *(const uint4*)&Whg[(size_t)(n0 + r) * K2 + k2 + c4];
            *(uint4*)&Wl[r * GST + c4] = *(const uint4*)&Wlg[(size_t)(n0 + r) * K2 + k2 + c4];
        }
        __syncthreads();

#pragma unroll
        for (int kk = 0; kk < 4; kk++) {
            const int k8 = kk * 8;
            unsigned ah[2][4], al[2][4], bh[4][2], bl[4][2];
#pragma unroll
            for (int mt = 0; mt < 2; mt++) {
                int R = wm * 32 + mt * 16;
                ah[mt][0] = Ah[(R + g) * GST + k8 + t];
                ah[mt][1] = Ah[(R + g + 8) * GST + k8 + t];
                ah[mt][2] = Ah[(R + g) * GST + k8 + 4 + t];
                ah[mt][3] = Ah[(R + g + 8) * GST + k8 + 4 + t];
                al[mt][0] = Al[(R + g) * GST + k8 + t];
                al[mt][1] = Al[(R + g + 8) * GST + k8 + t];
                al[mt][2] = Al[(R + g) * GST + k8 + 4 + t];
                al[mt][3] = Al[(R + g + 8) * GST + k8 + 4 + t];
            }
#pragma unroll
            for (int nt = 0; nt < 4; nt++) {
                int Cc = wn * 32 + nt * 8;
                bh[nt][0] = Wh[(Cc + g) * GST + k8 + t];
                bh[nt][1] = Wh[(Cc + g) * GST + k8 + 4 + t];
                bl[nt][0] = Wl[(Cc + g) * GST + k8 + t];
                bl[nt][1] = Wl[(Cc + g) * GST + k8 + 4 + t];
            }
#pragma unroll
            for (int mt = 0; mt < 2; mt++)
#pragma unroll
                for (int nt = 0; nt < 4; nt++)
                    mma_split(acc[mt][nt], ah[mt], al[mt], bh[nt], bl[nt]);
        }
        __syncthreads();
    }

#pragma unroll
    for (int mt = 0; mt < 2; mt++)
#pragma unroll
        for (int nt = 0; nt < 4; nt++)
#pragma unroll
            for (int r = 0; r < 4; r++) {
                int row = m0 + wm * 32 + mt * 16 + g + ((r >> 1) << 3);
                int col = n0 + wn * 32 + nt * 8 + t * 2 + (r & 1);
                float v = acc[mt][nt][r];
                if (mode == 0) {
                    int b = row / S_, s = row - b * S_;
                    int h = col >> 6, d = col & 63;
                    C[(((size_t)b * heads + h) * S_ + s) * HD_ + d] = v;
                } else {
                    C[(size_t)row * N + col] = v;
                }
            }
}

// ---------------- RoPE ----------------------------------------------------------
__global__ void rope_table_kernel()
{
    int idx = blockIdx.x * blockDim.x + threadIdx.x;
    if (idx >= S_ * 32) return;
    int j = idx & 31;
    int s = idx >> 5;
    double invf = pow(100000.0, -(double)(2 * j) / 64.0);
    double ang = (double)s * invf;
    g_cos[idx] = (float)cos(ang);
    g_sin[idx] = (float)sin(ang);
}

// rope + split-pack: 16 threads per row, thread j handles dims (2j,2j+1),(2j+32,2j+33)
__global__ void rope_apply_pack(const float* __restrict__ buf,
    unsigned* __restrict__ oh, unsigned* __restrict__ ol, int rows, float scale)
{
    int idx = blockIdx.x * blockDim.x + threadIdx.x;
    int j = idx & 15;
    int row = idx >> 4;
    if (row >= rows) return;
    int s = row & (S_ - 1);
    const float* p = buf + (size_t)row * HD_;
    float2 c  = *(const float2*)&g_cos[s * 32 + 2 * j];
    float2 sn = *(const float2*)&g_sin[s * 32 + 2 * j];
    float x00 = p[2 * j], x01 = p[2 * j + 1], x10 = p[2 * j + 32], x11 = p[2 * j + 33];
    float y0 = (x00 * c.x - x10 * sn.x) * scale;
    float y1 = (x01 * c.y - x11 * sn.y) * scale;
    float z0 = (x10 * c.x + x00 * sn.x) * scale;
    float z1 = (x11 * c.y + x01 * sn.y) * scale;
    unsigned hi, lo;
    split_pack(y0, y1, hi, lo);
    oh[(size_t)row * 32 + j] = hi; ol[(size_t)row * 32 + j] = lo;
    split_pack(z0, z1, hi, lo);
    oh[(size_t)row * 32 + 16 + j] = hi; ol[(size_t)row * 32 + 16 + j] = lo;
}

// ---------------- V transpose + pack: [bh][s][d] -> [bh][d][s/2] -----------------
#define VTS 68   // smem stride (multiple of 4: float4 stores stay 16B-aligned)
__global__ __launch_bounds__(256) void vpack_kernel(
    const float* __restrict__ V, unsigned* __restrict__ vh, unsigned* __restrict__ vl)
{
    __shared__ float sm[64 * VTS];
    const int bh = blockIdx.y;
    const int k0 = blockIdx.x * 64;
    const int tid = threadIdx.x;
    const float* src = V + ((size_t)bh * S_ + k0) * HD_;
    for (int i = tid; i < 64 * 16; i += 256) {
        int r = i >> 4, d4 = (i & 15) << 2;
        *(float4*)&sm[r * VTS + d4] = *(const float4*)&src[r * HD_ + d4];
    }
    __syncthreads();
    for (int i = tid; i < 64 * 32; i += 256) {
        int d = i >> 5, c = i & 31;
        float v0 = sm[(2 * c) * VTS + d];
        float v1 = sm[(2 * c + 1) * VTS + d];
        unsigned hi, lo;
        split_pack(v0, v1, hi, lo);
        size_t o = ((size_t)bh * HD_ + d) * (S_ / 2) + k0 / 2 + c;
        vh[o] = hi; vl[o] = lo;
    }
}

// ---------------- Flash attention (bf16-split mma) -------------------------------
#define AST 36
#define SST2 68
// smem u32 layout
#define OFF_QH 0
#define OFF_QL (OFF_QH + 64 * AST)
#define OFF_KH (OFF_QL + 64 * AST)
#define OFF_KL (OFF_KH + 64 * AST)
#define OFF_VH (OFF_KL + 64 * AST)
#define OFF_VL (OFF_VH + 64 * AST)
#define OFF_PH (OFF_VL + 64 * AST)
#define OFF_PL (OFF_PH + 64 * AST)
#define OFF_SS (OFF_PL + 64 * AST)
#define OFF_AL (OFF_SS + 64 * SST2)
#define OFF_LI (OFF_AL + 64)
#define ATT_SMEM ((OFF_LI + 64) * 4)

__global__ __launch_bounds__(256) void attn_tc_kernel(
    const unsigned* __restrict__ Qh, const unsigned* __restrict__ Ql,
    const unsigned* __restrict__ Kh, const unsigned* __restrict__ Kl,
    const unsigned* __restrict__ Vth, const unsigned* __restrict__ Vtl,
    unsigned* __restrict__ Ohg, unsigned* __restrict__ Olg)
{
    extern __shared__ unsigned smu[];
    unsigned* sQh = smu + OFF_QH;
    unsigned* sQl = smu + OFF_QL;
    unsigned* sKh = smu + OFF_KH;
    unsigned* sKl = smu + OFF_KL;
    unsigned* sVh = smu + OFF_VH;
    unsigned* sVl = smu + OFF_VL;
    unsigned* sPh = smu + OFF_PH;
    unsigned* sPl = smu + OFF_PL;
    float* Ss = (float*)(smu + OFF_SS);
    float* salpha = (float*)(smu + OFF_AL);
    float* slinv  = (float*)(smu + OFF_LI);

    const int bh = blockIdx.y;
    const int b = bh / NH_;
    const int h = bh - b * NH_;
    const int kvh = h / (NH_ / NKV_);
    const int q0 = (gridDim.x - 1 - blockIdx.x) * 64;

    const int tid = threadIdx.x;
    const int w = tid >> 5;
    const int lane = tid & 31;
    const int g = lane >> 2;
    const int t = lane & 3;
    const int wm = w >> 2;
    const int wn = w & 3;

    const unsigned* Qbh = Qh + ((size_t)bh * S_ + q0) * 32;
    const unsigned* Qbl = Ql + ((size_t)bh * S_ + q0) * 32;
    const unsigned* Kbh = Kh + ((size_t)(b * NKV_ + kvh) * S_) * 32;
    const unsigned* Kbl = Kl + ((size_t)(b * NKV_ + kvh) * S_) * 32;
    const unsigned* Vbh = Vth + (size_t)(b * NKV_ + kvh) * HD_ * (S_ / 2);
    const unsigned* Vbl = Vtl + (size_t)(b * NKV_ + kvh) * HD_ * (S_ / 2);

    // load Q (packed rows of 32 u32)
    for (int i = tid; i < 64 * 8; i += 256) {
        int r = i >> 3, c4 = (i & 7) << 2;
        *(uint4*)&sQh[r * AST + c4] = *(const uint4*)&Qbh[(size_t)r * 32 + c4];
        *(uint4*)&sQl[r * AST + c4] = *(const uint4*)&Qbl[(size_t)r * 32 + c4];
    }

    float acc[2][2][4];
#pragma unroll
    for (int mt = 0; mt < 2; mt++)
#pragma unroll
        for (int nt = 0; nt < 2; nt++)
#pragma unroll
            for (int r = 0; r < 4; r++) acc[mt][nt][r] = 0.f;

    float m_i[8], l_i[8];
#pragma unroll
    for (int r = 0; r < 8; r++) { m_i[r] = -1e30f; l_i[r] = 0.f; }

    const int nkt = q0 / 64 + 1;

    for (int kt = 0; kt < nkt; kt++) {
        const int k0 = kt * 64;
        __syncthreads();   // prior PV done

        for (int i = tid; i < 64 * 8; i += 256) {
            int r = i >> 3, c4 = (i & 7) << 2;
            *(uint4*)&sKh[r * AST + c4] = *(const uint4*)&Kbh[(size_t)(k0 + r) * 32 + c4];
            *(uint4*)&sKl[r * AST + c4] = *(const uint4*)&Kbl[(size_t)(k0 + r) * 32 + c4];
            *(uint4*)&sVh[r * AST + c4] = *(const uint4*)&Vbh[(size_t)r * (S_ / 2) + k0 / 2 + c4];
            *(uint4*)&sVl[r * AST + c4] = *(const uint4*)&Vbl[(size_t)r * (S_ / 2) + k0 / 2 + c4];
        }
        __syncthreads();

        // ---- scores: warp tile 32x16
        float sacc[2][2][4];
#pragma unroll
        for (int mt = 0; mt < 2; mt++)
#pragma unroll
            for (int nt = 0; nt < 2; nt++)
#pragma unroll
                for (int r = 0; r < 4; r++) sacc[mt][nt][r] = 0.f;

#pragma unroll
        for (int kk = 0; kk < 4; kk++) {
            const int k8 = kk * 8;
            unsigned ah[2][4], al[2][4], bh2[2][2], bl2[2][2];
#pragma unroll
            for (int mt = 0; mt < 2; mt++) {
                int R = wm * 32 + mt * 16;
                ah[mt][0] = sQh[(R + g) * AST + k8 + t];
                ah[mt][1] = sQh[(R + g + 8) * AST + k8 + t];
                ah[mt][2] = sQh[(R + g) * AST + k8 + 4 + t];
                ah[mt][3] = sQh[(R + g + 8) * AST + k8 + 4 + t];
                al[mt][0] = sQl[(R + g) * AST + k8 + t];
                al[mt][1] = sQl[(R + g + 8) * AST + k8 + t];
                al[mt][2] = sQl[(R + g) * AST + k8 + 4 + t];
                al[mt][3] = sQl[(R + g + 8) * AST + k8 + 4 + t];
            }
#pragma unroll
            for (int nt = 0; nt < 2; nt++) {
                int Cc = wn * 16 + nt * 8;
                bh2[nt][0] = sKh[(Cc + g) * AST + k8 + t];
                bh2[nt][1] = sKh[(Cc + g) * AST + k8 + 4 + t];
                bl2[nt][0] = sKl[(Cc + g) * AST + k8 + t];
                bl2[nt][1] = sKl[(Cc + g) * AST + k8 + 4 + t];
            }
#pragma unroll
            for (int mt = 0; mt < 2; mt++)
#pragma unroll
                for (int nt = 0; nt < 2; nt++)
                    mma_split(sacc[mt][nt], ah[mt], al[mt], bh2[nt], bl2[nt]);
        }

        const bool diag = (kt == nkt - 1);
#pragma unroll
        for (int mt = 0; mt < 2; mt++)
#pragma unroll
            for (int nt = 0; nt < 2; nt++)
#pragma unroll
                for (int rr = 0; rr < 2; rr++) {
                    int row = wm * 32 + mt * 16 + g + rr * 8;
                    int col = wn * 16 + nt * 8 + 2 * t;
                    float v0 = sacc[mt][nt][rr * 2];
                    float v1 = sacc[mt][nt][rr * 2 + 1];
                    if (diag) {
                        if (k0 + col > q0 + row)     v0 = -1e30f;
                        if (k0 + col + 1 > q0 + row) v1 = -1e30f;
                    }
                    *(float2*)&Ss[row * SST2 + col] = make_float2(v0, v1);
                }
        __syncthreads();

        // ---- online softmax: warp w rows w*8..w*8+7; lane -> cols 2lane,2lane+1
#pragma unroll
        for (int r = 0; r < 8; r++) {
            int row = w * 8 + r;
            float2 s01 = *(float2*)&Ss[row * SST2 + 2 * lane];
            float mt2 = fmaxf(s01.x, s01.y);
#pragma unroll
            for (int off = 16; off > 0; off >>= 1)
                mt2 = fmaxf(mt2, __shfl_xor_sync(0xffffffffu, mt2, off));
            float mn = fmaxf(m_i[r], mt2);
            float alpha = __expf(m_i[r] - mn);
            float p0 = __expf(s01.x - mn);
            float p1 = __expf(s01.y - mn);
            float ps = p0 + p1;
#pragma unroll
            for (int off = 16; off > 0; off >>= 1)
                ps += __shfl_xor_sync(0xffffffffu, ps, off);
            l_i[r] = l_i[r] * alpha + ps;
            m_i[r] = mn;
            unsigned hi, lo;
            split_pack(p0, p1, hi, lo);
            sPh[row * AST + lane] = hi;
            sPl[row * AST + lane] = lo;
            if (lane == 0) salpha[row] = alpha;
        }
        __syncthreads();

        // ---- rescale acc, then PV
        {
            float a0 = salpha[wm * 32 + g];
            float a1 = salpha[wm * 32 + g + 8];
            float a2 = salpha[wm * 32 + 16 + g];
            float a3 = salpha[wm * 32 + 16 + g + 8];
#pragma unroll
            for (int nt = 0; nt < 2; nt++) {
                acc[0][nt][0] *= a0; acc[0][nt][1] *= a0;
                acc[0][nt][2] *= a1; acc[0][nt][3] *= a1;
                acc[1][nt][0] *= a2; acc[1][nt][1] *= a2;
                acc[1][nt][2] *= a3; acc[1][nt][3] *= a3;
            }
        }

#pragma unroll
        for (int kk = 0; kk < 4; kk++) {
            const int k8 = kk * 8;
            unsigned ah[2][4], al[2][4], bh2[2][2], bl2[2][2];
#pragma unroll
            for (int mt = 0; mt < 2; mt++) {
                int R = wm * 32 + mt * 16;
                ah[mt][0] = sPh[(R + g) * AST + k8 + t];
                ah[mt][1] = sPh[(R + g + 8) * AST + k8 + t];
                ah[mt][2] = sPh[(R + g) * AST + k8 + 4 + t];
                ah[mt][3] = sPh[(R + g + 8) * AST + k8 + 4 + t];
                al[mt][0] = sPl[(R + g) * AST + k8 + t];
                al[mt][1] = sPl[(R + g + 8) * AST + k8 + t];
                al[mt][2] = sPl[(R + g) * AST + k8 + 4 + t];
                al[mt][3] = sPl[(R + g + 8) * AST + k8 + 4 + t];
            }
#pragma unroll
            for (int nt = 0; nt < 2; nt++) {
                int Cc = wn * 16 + nt * 8;
                bh2[nt][0] = sVh[(Cc + g) * AST + k8 + t];
                bh2[nt][1] = sVh[(Cc + g) * AST + k8 + 4 + t];
                bl2[nt][0] = sVl[(Cc + g) * AST + k8 + t];
                bl2[nt][1] = sVl[(Cc + g) * AST + k8 + 4 + t];
            }
#pragma unroll
            for (int mt = 0; mt < 2; mt++)
#pragma unroll
                for (int nt = 0; nt < 2; nt++)
                    mma_split(acc[mt][nt], ah[mt], al[mt], bh2[nt], bl2[nt]);
        }
    }

    // ---- epilogue: normalize, pack, write packed O for the O-projection
#pragma unroll
    for (int r = 0; r < 8; r++)
        if (lane == 0) slinv[w * 8 + r] = 1.f / l_i[r];
    __syncthreads();

#pragma unroll
    for (int mt = 0; mt < 2; mt++) {
        int R = wm * 32 + mt * 16;
        float i0 = slinv[R + g];
        float i1 = slinv[R + g + 8];
#pragma unroll
        for (int nt = 0; nt < 2; nt++)
#pragma unroll
            for (int rr = 0; rr < 2; rr++) {
                float inv = rr ? i1 : i0;
                int row = R + g + rr * 8;
                float v0 = acc[mt][nt][rr * 2] * inv;
                float v1 = acc[mt][nt][rr * 2 + 1] * inv;
                int s = q0 + row;
                size_t token = (size_t)b * S_ + s;
                int col2 = h * 32 + wn * 8 + nt * 4 + t;
                unsigned hi, lo;
                split_pack(v0, v1, hi, lo);
                Ohg[token * K2_ + col2] = hi;
                Olg[token * K2_ + col2] = lo;
            }
    }
}

// ---------------- launch ----------------------------------------------------------
extern "C" void kernel_launch(void* const* d_in, const int* in_sizes, int n_in,
                              void* d_out, int out_size)
{
    const float* x  = (const float*)d_in[0];
    const float* Wq = (const float*)d_in[1];
    const float* Wk = (const float*)d_in[2];
    const float* Wv = (const float*)d_in[3];
    const float* Wo = (const float*)d_in[4];
    float* out = (float*)d_out;

    float *qp, *kp, *vp;
    unsigned *xh, *xl, *wqh, *wql, *wkh, *wkl, *wvh, *wvl, *woh, *wol;
    unsigned *qh, *ql, *kh, *kl, *vth, *vtl, *oh, *ol;
    cudaGetSymbolAddress((void**)&qp, g_q);
    cudaGetSymbolAddress((void**)&kp, g_k);
    cudaGetSymbolAddress((void**)&vp, g_v);
    cudaGetSymbolAddress((void**)&xh, g_xh);   cudaGetSymbolAddress((void**)&xl, g_xl);
    cudaGetSymbolAddress((void**)&wqh, g_wqh); cudaGetSymbolAddress((void**)&wql, g_wql);
    cudaGetSymbolAddress((void**)&wkh, g_wkh); cudaGetSymbolAddress((void**)&wkl, g_wkl);
    cudaGetSymbolAddress((void**)&wvh, g_wvh); cudaGetSymbolAddress((void**)&wvl, g_wvl);
    cudaGetSymbolAddress((void**)&woh, g_woh); cudaGetSymbolAddress((void**)&wol, g_wol);
    cudaGetSymbolAddress((void**)&qh, g_qh);   cudaGetSymbolAddress((void**)&ql, g_ql);
    cudaGetSymbolAddress((void**)&kh, g_kh);   cudaGetSymbolAddress((void**)&kl, g_kl);
    cudaGetSymbolAddress((void**)&vth, g_vth); cudaGetSymbolAddress((void**)&vtl, g_vtl);
    cudaGetSymbolAddress((void**)&oh, g_oh);   cudaGetSymbolAddress((void**)&ol, g_ol);

    rope_table_kernel<<<(S_ * 32 + 255) / 256, 256>>>();

    // prepass: split-pack x and weights
    split_pack_kernel<<<(M_TOK * K2_ + 255) / 256, 256>>>(x, xh, xl, M_TOK * K2_);
    split_pack_kernel<<<(H_ * K2_ + 255) / 256, 256>>>(Wq, wqh, wql, H_ * K2_);
    split_pack_kernel<<<(NKV_ * HD_ * K2_ + 255) / 256, 256>>>(Wk, wkh, wkl, NKV_ * HD_ * K2_);
    split_pack_kernel<<<(NKV_ * HD_ * K2_ + 255) / 256, 256>>>(Wv, wvh, wvl, NKV_ * HD_ * K2_);
    split_pack_kernel<<<(H_ * K2_ + 255) / 256, 256>>>(Wo, woh, wol, H_ * K2_);

    cudaFuncSetAttribute(gemm_tc, cudaFuncAttributeMaxDynamicSharedMemorySize, GEMM_SMEM);

    // projections (float head-major out)
    gemm_tc<<<dim3(9, 64), 256, GEMM_SMEM>>>(xh, xl, wqh, wql, qp, NH_ * HD_, K2_, NH_, 0);
    gemm_tc<<<dim3(3, 64), 256, GEMM_SMEM>>>(xh, xl, wkh, wkl, kp, NKV_ * HD_, K2_, NKV_, 0);
    gemm_tc<<<dim3(3, 64), 256, GEMM_SMEM>>>(xh, xl, wvh, wvl, vp, NKV_ * HD_, K2_, NKV_, 0);

    // rope + pack (q scaled by 1/sqrt(64))
    {
        int rows_q = B_ * NH_ * S_;
        int rows_k = B_ * NKV_ * S_;
        rope_apply_pack<<<(rows_q * 16 + 255) / 256, 256>>>(qp, qh, ql, rows_q, 0.125f);
        rope_apply_pack<<<(rows_k * 16 + 255) / 256, 256>>>(kp, kh, kl, rows_k, 1.0f);
    }

    // V transpose + pack
    vpack_kernel<<<dim3(S_ / 64, B_ * NKV_), 256>>>(vp, vth, vtl);

    // attention (packed output)
    cudaFuncSetAttribute(attn_tc_kernel, cudaFuncAttributeMaxDynamicSharedMemorySize, ATT_SMEM);
    attn_tc_kernel<<<dim3(S_ / 64, B_ * NH_), 256, ATT_SMEM>>>(qh, ql, kh, kl, vth, vtl, oh, ol);

    // O projection -> final float out
    gemm_tc<<<dim3(9, 64), 256, GEMM_SMEM>>>(oh, ol, woh, wol, out, H_, K2_, 0, 1);
}

// round 7
// speedup vs baseline: 3.9315x; 1.1986x over previous
#include <cuda_runtime.h>
#include <cuda_bf16.h>
#include <math.h>

#define B_ 4
#define S_ 2048
#define H_ 576
#define NH_ 9
#define NKV_ 3
#define HD_ 64
#define M_TOK (B_ * S_)   // 8192
#define K2_ (H_ / 2)      // 288 packed u32 per token row

// ---------------- scratch -----------------------------------------------------
__device__ float g_q[B_ * NH_ * S_ * HD_];
__device__ float g_k[B_ * NKV_ * S_ * HD_];
__device__ float g_v[B_ * NKV_ * S_ * HD_];
__device__ float g_cos[S_ * 32];
__device__ float g_sin[S_ * 32];

// packed bf16x2 hi/lo planes
__device__ unsigned g_xh[M_TOK * K2_],  g_xl[M_TOK * K2_];
__device__ unsigned g_wqh[H_ * K2_],    g_wql[H_ * K2_];
__device__ unsigned g_wkh[NKV_ * HD_ * K2_], g_wkl[NKV_ * HD_ * K2_];
__device__ unsigned g_wvh[NKV_ * HD_ * K2_], g_wvl[NKV_ * HD_ * K2_];
__device__ unsigned g_woh[H_ * K2_],    g_wol[H_ * K2_];
__device__ unsigned g_qh[B_ * NH_ * S_ * 32],  g_ql[B_ * NH_ * S_ * 32];
__device__ unsigned g_kh[B_ * NKV_ * S_ * 32], g_kl[B_ * NKV_ * S_ * 32];
__device__ unsigned g_vth[B_ * NKV_ * HD_ * (S_ / 2)], g_vtl[B_ * NKV_ * HD_ * (S_ / 2)];
__device__ unsigned g_oh[M_TOK * K2_],  g_ol[M_TOK * K2_];

// ---------------- helpers ------------------------------------------------------
__device__ __forceinline__ void split_pack(float x0, float x1, unsigned& hi, unsigned& lo)
{
    __nv_bfloat162 h = __float22bfloat162_rn(make_float2(x0, x1));
    float2 hf = __bfloat1622float2(h);
    __nv_bfloat162 l = __float22bfloat162_rn(make_float2(x0 - hf.x, x1 - hf.y));
    hi = *reinterpret_cast<unsigned*>(&h);
    lo = *reinterpret_cast<unsigned*>(&l);
}

__device__ __forceinline__ void mma16(float* c,
    unsigned a0, unsigned a1, unsigned a2, unsigned a3,
    unsigned b0, unsigned b1)
{
    asm volatile(
        "mma.sync.aligned.m16n8k16.row.col.f32.bf16.bf16.f32 "
        "{%0,%1,%2,%3},{%4,%5,%6,%7},{%8,%9},{%0,%1,%2,%3};"
        : "+f"(c[0]), "+f"(c[1]), "+f"(c[2]), "+f"(c[3])
        : "r"(a0), "r"(a1), "r"(a2), "r"(a3), "r"(b0), "r"(b1));
}
__device__ __forceinline__ void mma_split(float* c,
    const unsigned* ah, const unsigned* al,
    const unsigned* bh, const unsigned* bl)
{
    mma16(c, ah[0], ah[1], ah[2], ah[3], bh[0], bh[1]);
    mma16(c, ah[0], ah[1], ah[2], ah[3], bl[0], bl[1]);
    mma16(c, al[0], al[1], al[2], al[3], bh[0], bh[1]);
}

// ---------------- prepass: split float matrix to packed planes ------------------
__global__ void split_pack_kernel(const float* __restrict__ src,
                                  unsigned* __restrict__ hi, unsigned* __restrict__ lo, int n2)
{
    int i = blockIdx.x * blockDim.x + threadIdx.x;
    if (i >= n2) return;
    float2 v = ((const float2*)src)[i];
    split_pack(v.x, v.y, hi[i], lo[i]);
}

// ---------------- tensor-core GEMM on packed planes -----------------------------
#define GST 36
#define GEMM_SMEM ((128 * GST * 2 + 64 * GST * 2) * 4)

__global__ __launch_bounds__(256) void gemm_tc(
    const unsigned* __restrict__ Ahg, const unsigned* __restrict__ Alg,
    const unsigned* __restrict__ Whg, const unsigned* __restrict__ Wlg,
    float* __restrict__ C, int N, int K2, int heads, int mode)
{
    extern __shared__ unsigned smu[];
    unsigned* Ah = smu;
    unsigned* Al = smu + 128 * GST;
    unsigned* Wh = smu + 2 * 128 * GST;
    unsigned* Wl = Wh + 64 * GST;

    const int tid = threadIdx.x;
    const int w = tid >> 5;
    const int lane = tid & 31;
    const int g = lane >> 2;
    const int t = lane & 3;
    const int wm = w >> 1;
    const int wn = w & 1;
    const int m0 = blockIdx.y * 128;
    const int n0 = blockIdx.x * 64;

    float acc[2][4][4];
#pragma unroll
    for (int mt = 0; mt < 2; mt++)
#pragma unroll
        for (int nt = 0; nt < 4; nt++)
#pragma unroll
            for (int r = 0; r < 4; r++) acc[mt][nt][r] = 0.f;

    for (int k2 = 0; k2 < K2; k2 += 32) {
#pragma unroll
        for (int i = tid; i < 128 * 8; i += 256) {
            int r = i >> 3, c4 = (i & 7) << 2;
            *(uint4*)&Ah[r * GST + c4] = *(const uint4*)&Ahg[(size_t)(m0 + r) * K2 + k2 + c4];
            *(uint4*)&Al[r * GST + c4] = *(const uint4*)&Alg[(size_t)(m0 + r) * K2 + k2 + c4];
        }
#pragma unroll
        for (int i = tid; i < 64 * 8; i += 256) {
            int r = i >> 3, c4 = (i & 7) << 2;
            *(uint4*)&Wh[r * GST + c4] = *(const uint4*)&Whg[(size_t)(n0 + r) * K2 + k2 + c4];
            *(uint4*)&Wl[r * GST + c4] = *(const uint4*)&Wlg[(size_t)(n0 + r) * K2 + k2 + c4];
        }
        __syncthreads();

#pragma unroll
        for (int kk = 0; kk < 4; kk++) {
            const int k8 = kk * 8;
            unsigned ah[2][4], al[2][4], bh[4][2], bl[4][2];
#pragma unroll
            for (int mt = 0; mt < 2; mt++) {
                int R = wm * 32 + mt * 16;
                ah[mt][0] = Ah[(R + g) * GST + k8 + t];
                ah[mt][1] = Ah[(R + g + 8) * GST + k8 + t];
                ah[mt][2] = Ah[(R + g) * GST + k8 + 4 + t];
                ah[mt][3] = Ah[(R + g + 8) * GST + k8 + 4 + t];
                al[mt][0] = Al[(R + g) * GST + k8 + t];
                al[mt][1] = Al[(R + g + 8) * GST + k8 + t];
                al[mt][2] = Al[(R + g) * GST + k8 + 4 + t];
                al[mt][3] = Al[(R + g + 8) * GST + k8 + 4 + t];
            }
#pragma unroll
            for (int nt = 0; nt < 4; nt++) {
                int Cc = wn * 32 + nt * 8;
                bh[nt][0] = Wh[(Cc + g) * GST + k8 + t];
                bh[nt][1] = Wh[(Cc + g) * GST + k8 + 4 + t];
                bl[nt][0] = Wl[(Cc + g) * GST + k8 + t];
                bl[nt][1] = Wl[(Cc + g) * GST + k8 + 4 + t];
            }
#pragma unroll
            for (int mt = 0; mt < 2; mt++)
#pragma unroll
                for (int nt = 0; nt < 4; nt++)
                    mma_split(acc[mt][nt], ah[mt], al[mt], bh[nt], bl[nt]);
        }
        __syncthreads();
    }

#pragma unroll
    for (int mt = 0; mt < 2; mt++)
#pragma unroll
        for (int nt = 0; nt < 4; nt++)
#pragma unroll
            for (int r = 0; r < 4; r++) {
                int row = m0 + wm * 32 + mt * 16 + g + ((r >> 1) << 3);
                int col = n0 + wn * 32 + nt * 8 + t * 2 + (r & 1);
                float v = acc[mt][nt][r];
                if (mode == 0) {
                    int b = row / S_, s = row - b * S_;
                    int h = col >> 6, d = col & 63;
                    C[(((size_t)b * heads + h) * S_ + s) * HD_ + d] = v;
                } else {
                    C[(size_t)row * N + col] = v;
                }
            }
}

// ---------------- RoPE ----------------------------------------------------------
__global__ void rope_table_kernel()
{
    int idx = blockIdx.x * blockDim.x + threadIdx.x;
    if (idx >= S_ * 32) return;
    int j = idx & 31;
    int s = idx >> 5;
    double invf = pow(100000.0, -(double)(2 * j) / 64.0);
    double ang = (double)s * invf;
    g_cos[idx] = (float)cos(ang);
    g_sin[idx] = (float)sin(ang);
}

__global__ void rope_apply_pack(const float* __restrict__ buf,
    unsigned* __restrict__ oh, unsigned* __restrict__ ol, int rows, float scale)
{
    int idx = blockIdx.x * blockDim.x + threadIdx.x;
    int j = idx & 15;
    int row = idx >> 4;
    if (row >= rows) return;
    int s = row & (S_ - 1);
    const float* p = buf + (size_t)row * HD_;
    float2 c  = *(const float2*)&g_cos[s * 32 + 2 * j];
    float2 sn = *(const float2*)&g_sin[s * 32 + 2 * j];
    float x00 = p[2 * j], x01 = p[2 * j + 1], x10 = p[2 * j + 32], x11 = p[2 * j + 33];
    float y0 = (x00 * c.x - x10 * sn.x) * scale;
    float y1 = (x01 * c.y - x11 * sn.y) * scale;
    float z0 = (x10 * c.x + x00 * sn.x) * scale;
    float z1 = (x11 * c.y + x01 * sn.y) * scale;
    unsigned hi, lo;
    split_pack(y0, y1, hi, lo);
    oh[(size_t)row * 32 + j] = hi; ol[(size_t)row * 32 + j] = lo;
    split_pack(z0, z1, hi, lo);
    oh[(size_t)row * 32 + 16 + j] = hi; ol[(size_t)row * 32 + 16 + j] = lo;
}

// ---------------- V transpose + pack ----------------------------------------------
#define VTS 68
__global__ __launch_bounds__(256) void vpack_kernel(
    const float* __restrict__ V, unsigned* __restrict__ vh, unsigned* __restrict__ vl)
{
    __shared__ float sm[64 * VTS];
    const int bh = blockIdx.y;
    const int k0 = blockIdx.x * 64;
    const int tid = threadIdx.x;
    const float* src = V + ((size_t)bh * S_ + k0) * HD_;
    for (int i = tid; i < 64 * 16; i += 256) {
        int r = i >> 4, d4 = (i & 15) << 2;
        *(float4*)&sm[r * VTS + d4] = *(const float4*)&src[r * HD_ + d4];
    }
    __syncthreads();
    for (int i = tid; i < 64 * 32; i += 256) {
        int d = i >> 5, c = i & 31;
        float v0 = sm[(2 * c) * VTS + d];
        float v1 = sm[(2 * c + 1) * VTS + d];
        unsigned hi, lo;
        split_pack(v0, v1, hi, lo);
        size_t o = ((size_t)bh * HD_ + d) * (S_ / 2) + k0 / 2 + c;
        vh[o] = hi; vl[o] = lo;
    }
}

// ---------------- Flash attention (register-resident P, q-tile 128) ---------------
#define AST 36
#define OFF_QH 0
#define OFF_QL (OFF_QH + 128 * AST)
#define OFF_KH (OFF_QL + 128 * AST)
#define OFF_KL (OFF_KH + 64 * AST)
#define OFF_VH (OFF_KL + 64 * AST)
#define OFF_VL (OFF_VH + 64 * AST)
#define ATT_SMEM ((OFF_VL + 64 * AST) * 4)

__global__ __launch_bounds__(256, 2) void attn_tc_kernel(
    const unsigned* __restrict__ Qh, const unsigned* __restrict__ Ql,
    const unsigned* __restrict__ Kh, const unsigned* __restrict__ Kl,
    const unsigned* __restrict__ Vth, const unsigned* __restrict__ Vtl,
    unsigned* __restrict__ Ohg, unsigned* __restrict__ Olg)
{
    extern __shared__ unsigned smu[];
    unsigned* sQh = smu + OFF_QH;
    unsigned* sQl = smu + OFF_QL;
    unsigned* sKh = smu + OFF_KH;
    unsigned* sKl = smu + OFF_KL;
    unsigned* sVh = smu + OFF_VH;
    unsigned* sVl = smu + OFF_VL;

    const int bh = blockIdx.y;
    const int b = bh / NH_;
    const int h = bh - b * NH_;
    const int kvh = h / (NH_ / NKV_);
    const int q0 = (gridDim.x - 1 - blockIdx.x) * 128;   // heavy tiles first

    const int tid = threadIdx.x;
    const int w = tid >> 5;
    const int lane = tid & 31;
    const int g = lane >> 2;
    const int t = lane & 3;
    const int R0 = w * 16;        // warp's q-row base within tile

    const unsigned* Qbh = Qh + ((size_t)bh * S_ + q0) * 32;
    const unsigned* Qbl = Ql + ((size_t)bh * S_ + q0) * 32;
    const unsigned* Kbh = Kh + ((size_t)(b * NKV_ + kvh) * S_) * 32;
    const unsigned* Kbl = Kl + ((size_t)(b * NKV_ + kvh) * S_) * 32;
    const unsigned* Vbh = Vth + (size_t)(b * NKV_ + kvh) * HD_ * (S_ / 2);
    const unsigned* Vbl = Vtl + (size_t)(b * NKV_ + kvh) * HD_ * (S_ / 2);

    // load Q tile (128 rows x 32 u32, 2 planes)
    for (int i = tid; i < 128 * 4; i += 256) {
        int r = i >> 2, c4 = (i & 3) << 3;            // c4 in {0,8,16,24}
        *(uint4*)&sQh[r * AST + c4]     = *(const uint4*)&Qbh[(size_t)r * 32 + c4];
        *(uint4*)&sQh[r * AST + c4 + 4] = *(const uint4*)&Qbh[(size_t)r * 32 + c4 + 4];
        *(uint4*)&sQl[r * AST + c4]     = *(const uint4*)&Qbl[(size_t)r * 32 + c4];
        *(uint4*)&sQl[r * AST + c4 + 4] = *(const uint4*)&Qbl[(size_t)r * 32 + c4 + 4];
    }

    float acc[8][4];              // PV accumulator: 8 n-tiles (64 dims)
#pragma unroll
    for (int nt = 0; nt < 8; nt++)
#pragma unroll
        for (int r = 0; r < 4; r++) acc[nt][r] = 0.f;

    float m0 = -1e30f, m1 = -1e30f, l0 = 0.f, l1 = 0.f;

    const int nkt = q0 / 64 + 2;

    for (int kt = 0; kt < nkt; kt++) {
        const int k0 = kt * 64;
        __syncthreads();          // prev tile's mma reads of sK/sV done

        // load K and V tiles: 4 arrays x (64 rows x 32 u32) = 2048 uint4
        for (int i = tid; i < 2048; i += 256) {
            int sel = i >> 9;                 // 0..3
            int j = i & 511;
            int r = j >> 3, c4 = (j & 7) << 2;
            if (sel == 0)
                *(uint4*)&sKh[r * AST + c4] = *(const uint4*)&Kbh[(size_t)(k0 + r) * 32 + c4];
            else if (sel == 1)
                *(uint4*)&sKl[r * AST + c4] = *(const uint4*)&Kbl[(size_t)(k0 + r) * 32 + c4];
            else if (sel == 2)
                *(uint4*)&sVh[r * AST + c4] = *(const uint4*)&Vbh[(size_t)r * (S_ / 2) + k0 / 2 + c4];
            else
                *(uint4*)&sVl[r * AST + c4] = *(const uint4*)&Vbl[(size_t)r * (S_ / 2) + k0 / 2 + c4];
        }
        __syncthreads();

        // ---- scores: this warp: 16 q rows x 64 kv cols (8 n-tiles)
        float sacc[8][4];
#pragma unroll
        for (int nt = 0; nt < 8; nt++)
#pragma unroll
            for (int r = 0; r < 4; r++) sacc[nt][r] = 0.f;

#pragma unroll
        for (int kk = 0; kk < 4; kk++) {
            const int k8 = kk * 8;
            unsigned qh[4], ql[4];
            qh[0] = sQh[(R0 + g) * AST + k8 + t];
            qh[1] = sQh[(R0 + g + 8) * AST + k8 + t];
            qh[2] = sQh[(R0 + g) * AST + k8 + 4 + t];
            qh[3] = sQh[(R0 + g + 8) * AST + k8 + 4 + t];
            ql[0] = sQl[(R0 + g) * AST + k8 + t];
            ql[1] = sQl[(R0 + g + 8) * AST + k8 + t];
            ql[2] = sQl[(R0 + g) * AST + k8 + 4 + t];
            ql[3] = sQl[(R0 + g + 8) * AST + k8 + 4 + t];
#pragma unroll
            for (int nt = 0; nt < 8; nt++) {
                unsigned bh2[2], bl2[2];
                bh2[0] = sKh[(nt * 8 + g) * AST + k8 + t];
                bh2[1] = sKh[(nt * 8 + g) * AST + k8 + 4 + t];
                bl2[0] = sKl[(nt * 8 + g) * AST + k8 + t];
                bl2[1] = sKl[(nt * 8 + g) * AST + k8 + 4 + t];
                mma_split(sacc[nt], qh, ql, bh2, bl2);
            }
        }

        // ---- causal mask (only near the diagonal)
        if (kt >= nkt - 2) {
            int row0 = q0 + R0 + g;
            int row1 = row0 + 8;
#pragma unroll
            for (int nt = 0; nt < 8; nt++) {
                int col = k0 + nt * 8 + 2 * t;
                if (col > row0)     sacc[nt][0] = -1e30f;
                if (col + 1 > row0) sacc[nt][1] = -1e30f;
                if (col > row1)     sacc[nt][2] = -1e30f;
                if (col + 1 > row1) sacc[nt][3] = -1e30f;
            }
        }

        // ---- online softmax in registers (quad reductions)
        float rmax0 = -1e30f, rmax1 = -1e30f;
#pragma unroll
        for (int nt = 0; nt < 8; nt++) {
            rmax0 = fmaxf(rmax0, fmaxf(sacc[nt][0], sacc[nt][1]));
            rmax1 = fmaxf(rmax1, fmaxf(sacc[nt][2], sacc[nt][3]));
        }
        rmax0 = fmaxf(rmax0, __shfl_xor_sync(0xffffffffu, rmax0, 1));
        rmax0 = fmaxf(rmax0, __shfl_xor_sync(0xffffffffu, rmax0, 2));
        rmax1 = fmaxf(rmax1, __shfl_xor_sync(0xffffffffu, rmax1, 1));
        rmax1 = fmaxf(rmax1, __shfl_xor_sync(0xffffffffu, rmax1, 2));

        float mn0 = fmaxf(m0, rmax0);
        float mn1 = fmaxf(m1, rmax1);
        float alpha0 = __expf(m0 - mn0);
        float alpha1 = __expf(m1 - mn1);
        m0 = mn0; m1 = mn1;

        float rsum0 = 0.f, rsum1 = 0.f;
#pragma unroll
        for (int nt = 0; nt < 8; nt++) {
            sacc[nt][0] = __expf(sacc[nt][0] - mn0);
            sacc[nt][1] = __expf(sacc[nt][1] - mn0);
            sacc[nt][2] = __expf(sacc[nt][2] - mn1);
            sacc[nt][3] = __expf(sacc[nt][3] - mn1);
            rsum0 += sacc[nt][0] + sacc[nt][1];
            rsum1 += sacc[nt][2] + sacc[nt][3];
        }
        rsum0 += __shfl_xor_sync(0xffffffffu, rsum0, 1);
        rsum0 += __shfl_xor_sync(0xffffffffu, rsum0, 2);
        rsum1 += __shfl_xor_sync(0xffffffffu, rsum1, 1);
        rsum1 += __shfl_xor_sync(0xffffffffu, rsum1, 2);
        l0 = l0 * alpha0 + rsum0;
        l1 = l1 * alpha1 + rsum1;

        // rescale accumulator
#pragma unroll
        for (int nt = 0; nt < 8; nt++) {
            acc[nt][0] *= alpha0; acc[nt][1] *= alpha0;
            acc[nt][2] *= alpha1; acc[nt][3] *= alpha1;
        }

        // ---- PV: P fragments straight from sacc (C-frag == A-frag layout)
#pragma unroll
        for (int kk = 0; kk < 4; kk++) {
            unsigned ph[4], pl[4];
            split_pack(sacc[2 * kk][0],     sacc[2 * kk][1],     ph[0], pl[0]);
            split_pack(sacc[2 * kk][2],     sacc[2 * kk][3],     ph[1], pl[1]);
            split_pack(sacc[2 * kk + 1][0], sacc[2 * kk + 1][1], ph[2], pl[2]);
            split_pack(sacc[2 * kk + 1][2], sacc[2 * kk + 1][3], ph[3], pl[3]);
            const int k8 = kk * 8;
#pragma unroll
            for (int nt = 0; nt < 8; nt++) {
                unsigned bh2[2], bl2[2];
                bh2[0] = sVh[(nt * 8 + g) * AST + k8 + t];
                bh2[1] = sVh[(nt * 8 + g) * AST + k8 + 4 + t];
                bl2[0] = sVl[(nt * 8 + g) * AST + k8 + t];
                bl2[1] = sVl[(nt * 8 + g) * AST + k8 + 4 + t];
                mma_split(acc[nt], ph, pl, bh2, bl2);
            }
        }
    }

    // ---- epilogue: normalize, pack, write packed O for O-projection
    float inv0 = 1.f / l0;
    float inv1 = 1.f / l1;
    int row0 = q0 + R0 + g;
    int row1 = row0 + 8;
    size_t tok0 = (size_t)b * S_ + row0;
    size_t tok1 = (size_t)b * S_ + row1;
#pragma unroll
    for (int nt = 0; nt < 8; nt++) {
        int col2 = h * 32 + nt * 4 + t;
        unsigned hi, lo;
        split_pack(acc[nt][0] * inv0, acc[nt][1] * inv0, hi, lo);
        Ohg[tok0 * K2_ + col2] = hi;
        Olg[tok0 * K2_ + col2] = lo;
        split_pack(acc[nt][2] * inv1, acc[nt][3] * inv1, hi, lo);
        Ohg[tok1 * K2_ + col2] = hi;
        Olg[tok1 * K2_ + col2] = lo;
    }
}

// ---------------- launch ----------------------------------------------------------
extern "C" void kernel_launch(void* const* d_in, const int* in_sizes, int n_in,
                              void* d_out, int out_size)
{
    const float* x  = (const float*)d_in[0];
    const float* Wq = (const float*)d_in[1];
    const float* Wk = (const float*)d_in[2];
    const float* Wv = (const float*)d_in[3];
    const float* Wo = (const float*)d_in[4];
    float* out = (float*)d_out;

    float *qp, *kp, *vp;
    unsigned *xh, *xl, *wqh, *wql, *wkh, *wkl, *wvh, *wvl, *woh, *wol;
    unsigned *qh, *ql, *kh, *kl, *vth, *vtl, *oh, *ol;
    cudaGetSymbolAddress((void**)&qp, g_q);
    cudaGetSymbolAddress((void**)&kp, g_k);
    cudaGetSymbolAddress((void**)&vp, g_v);
    cudaGetSymbolAddress((void**)&xh, g_xh);   cudaGetSymbolAddress((void**)&xl, g_xl);
    cudaGetSymbolAddress((void**)&wqh, g_wqh); cudaGetSymbolAddress((void**)&wql, g_wql);
    cudaGetSymbolAddress((void**)&wkh, g_wkh); cudaGetSymbolAddress((void**)&wkl, g_wkl);
    cudaGetSymbolAddress((void**)&wvh, g_wvh); cudaGetSymbolAddress((void**)&wvl, g_wvl);
    cudaGetSymbolAddress((void**)&woh, g_woh); cudaGetSymbolAddress((void**)&wol, g_wol);
    cudaGetSymbolAddress((void**)&qh, g_qh);   cudaGetSymbolAddress((void**)&ql, g_ql);
    cudaGetSymbolAddress((void**)&kh, g_kh);   cudaGetSymbolAddress((void**)&kl, g_kl);
    cudaGetSymbolAddress((void**)&vth, g_vth); cudaGetSymbolAddress((void**)&vtl, g_vtl);
    cudaGetSymbolAddress((void**)&oh, g_oh);   cudaGetSymbolAddress((void**)&ol, g_ol);

    rope_table_kernel<<<(S_ * 32 + 255) / 256, 256>>>();

    split_pack_kernel<<<(M_TOK * K2_ + 255) / 256, 256>>>(x, xh, xl, M_TOK * K2_);
    split_pack_kernel<<<(H_ * K2_ + 255) / 256, 256>>>(Wq, wqh, wql, H_ * K2_);
    split_pack_kernel<<<(NKV_ * HD_ * K2_ + 255) / 256, 256>>>(Wk, wkh, wkl, NKV_ * HD_ * K2_);
    split_pack_kernel<<<(NKV_ * HD_ * K2_ + 255) / 256, 256>>>(Wv, wvh, wvl, NKV_ * HD_ * K2_);
    split_pack_kernel<<<(H_ * K2_ + 255) / 256, 256>>>(Wo, woh, wol, H_ * K2_);

    cudaFuncSetAttribute(gemm_tc, cudaFuncAttributeMaxDynamicSharedMemorySize, GEMM_SMEM);

    gemm_tc<<<dim3(9, 64), 256, GEMM_SMEM>>>(xh, xl, wqh, wql, qp, NH_ * HD_, K2_, NH_, 0);
    gemm_tc<<<dim3(3, 64), 256, GEMM_SMEM>>>(xh, xl, wkh, wkl, kp, NKV_ * HD_, K2_, NKV_, 0);
    gemm_tc<<<dim3(3, 64), 256, GEMM_SMEM>>>(xh, xl, wvh, wvl, vp, NKV_ * HD_, K2_, NKV_, 0);

    {
        int rows_q = B_ * NH_ * S_;
        int rows_k = B_ * NKV_ * S_;
        rope_apply_pack<<<(rows_q * 16 + 255) / 256, 256>>>(qp, qh, ql, rows_q, 0.125f);
        rope_apply_pack<<<(rows_k * 16 + 255) / 256, 256>>>(kp, kh, kl, rows_k, 1.0f);
    }

    vpack_kernel<<<dim3(S_ / 64, B_ * NKV_), 256>>>(vp, vth, vtl);

    cudaFuncSetAttribute(attn_tc_kernel, cudaFuncAttributeMaxDynamicSharedMemorySize, ATT_SMEM);
    attn_tc_kernel<<<dim3(S_ / 128, B_ * NH_), 256, ATT_SMEM>>>(qh, ql, kh, kl, vth, vtl, oh, ol);

    gemm_tc<<<dim3(9, 64), 256, GEMM_SMEM>>>(oh, ol, woh, wol, out, H_, K2_, 0, 1);
}